// round 1
// baseline (speedup 1.0000x reference)
#include <cuda_runtime.h>

#define NN  25000
#define NE  400000
#define NEF 425000   /* NE + NN self-loops */
#define D   128
#define NH  4
#define EFD 32
#define NL  6

/* ---------------- scratch (static device globals; no allocs) -------------- */
__device__ float g_h[NN * D];
__device__ float g_hm[NN * D];
__device__ float g_x[NN * NH * D];
__device__ float g_als[NN * NH];
__device__ float g_ald[NN * NH];
__device__ float g_ale[NEF * NH];
__device__ int   g_rowptr[NN + 1];
__device__ int   g_counts[NN];
__device__ int   g_fill[NN];
__device__ int   g_csrsrc[NEF];
__device__ int   g_csreid[NEF];
__device__ float g_eamean[EFD];
__device__ float g_partial[256 * EFD];
__device__ float g_v[NH * EFD];
__device__ float g_aleself[NH];
__device__ float g_t[NN * D];
__device__ float g_u[NN * D];
__device__ float g_p[NE * D];
__device__ int   g_bsums[32];

/* ---------------- helpers ---------------- */
__device__ __forceinline__ float wredsum(float v) {
    #pragma unroll
    for (int o = 16; o; o >>= 1) v += __shfl_xor_sync(0xffffffffu, v, o);
    return v;
}
__device__ __forceinline__ float wredmax(float v) {
    #pragma unroll
    for (int o = 16; o; o >>= 1) v = fmaxf(v, __shfl_xor_sync(0xffffffffu, v, o));
    return v;
}

/* ---------------- edge-attr mean (deterministic 2-stage) ---------------- */
__global__ void k_eamean1(const float* __restrict__ ea) {
    const int SPAN = 1563;
    int blk = blockIdx.x;
    int w = threadIdx.x >> 5, lane = threadIdx.x & 31;
    long start = (long)blk * SPAN;
    long end = start + SPAN; if (end > NE) end = NE;
    float s = 0.f;
    for (long e = start + w; e < end; e += 4) s += ea[e * EFD + lane];
    __shared__ float sm[4][32];
    sm[w][lane] = s;
    __syncthreads();
    if (w == 0) {
        float t = sm[0][lane] + sm[1][lane] + sm[2][lane] + sm[3][lane];
        g_partial[blk * 32 + lane] = t;
    }
}
__global__ void k_eamean2() {
    int lane = threadIdx.x;
    float s = 0.f;
    for (int b = 0; b < 256; b++) s += g_partial[b * 32 + lane];
    g_eamean[lane] = s * (1.f / (float)NE);
}

/* ---------------- CSR build ---------------- */
__global__ void k_init_counts() {
    int i = blockIdx.x * blockDim.x + threadIdx.x;
    if (i < NN) g_counts[i] = 1;   /* self loop */
}
__global__ void k_count(const int* __restrict__ dst) {
    int e = blockIdx.x * blockDim.x + threadIdx.x;
    if (e < NE) atomicAdd(&g_counts[dst[e]], 1);
}
__global__ void k_scan_local() {
    __shared__ int sm[1024];
    int base = blockIdx.x * 1024;
    int t = threadIdx.x;
    int v = (base + t < NN) ? g_counts[base + t] : 0;
    sm[t] = v;
    __syncthreads();
    #pragma unroll
    for (int off = 1; off < 1024; off <<= 1) {
        int x = (t >= off) ? sm[t - off] : 0;
        __syncthreads();
        sm[t] += x;
        __syncthreads();
    }
    if (base + t < NN) g_rowptr[base + t] = sm[t] - v;   /* exclusive */
    if (t == 1023) g_bsums[blockIdx.x] = sm[1023];
}
__global__ void k_scan_fixup(int nb) {
    if (threadIdx.x == 0) {
        int run = 0;
        for (int b = 0; b < nb; b++) { int t = g_bsums[b]; g_bsums[b] = run; run += t; }
        g_rowptr[NN] = run;
    }
}
__global__ void k_scan_add() {
    int i = blockIdx.x * blockDim.x + threadIdx.x;
    if (i < NN) {
        int r = g_rowptr[i] + g_bsums[i >> 10];
        g_rowptr[i] = r;
        g_fill[i] = r;
    }
}
__global__ void k_scatter_edges(const int* __restrict__ src, const int* __restrict__ dst) {
    int e = blockIdx.x * blockDim.x + threadIdx.x;
    if (e < NE) {
        int d = dst[e];
        int pos = atomicAdd(&g_fill[d], 1);
        g_csrsrc[pos] = src[e];
        g_csreid[pos] = e;
    }
}
__global__ void k_scatter_self() {
    int i = blockIdx.x * blockDim.x + threadIdx.x;
    if (i < NN) {
        int pos = atomicAdd(&g_fill[i], 1);
        g_csrsrc[pos] = i;
        g_csreid[pos] = NE + i;
    }
}

/* ---------------- fp32 GEMM: C[M,N] = A[M,K] @ B[K,N] (+bias) ---------------- */
/* BM=BN=128, BK=32, 256 threads, 8x8 micro tile */
__global__ void k_gemm(const float* __restrict__ A, const float* __restrict__ B,
                       float* __restrict__ C, int M, int N, int K,
                       const float* __restrict__ bias) {
    __shared__ float As[32][128];
    __shared__ float Bs[32][128];
    int bm = blockIdx.y * 128;
    int bn = blockIdx.x * 128;
    int tid = threadIdx.x;
    int tr = (tid / 16) * 8;
    int tc = (tid % 16) * 8;
    float acc[8][8];
    #pragma unroll
    for (int i = 0; i < 8; i++)
        #pragma unroll
        for (int j = 0; j < 8; j++) acc[i][j] = 0.f;

    for (int kk = 0; kk < K; kk += 32) {
        #pragma unroll
        for (int i = 0; i < 4; i++) {
            int r = tid / 8 + i * 32;
            int c = (tid % 8) * 4;
            float4 v = make_float4(0.f, 0.f, 0.f, 0.f);
            int gr = bm + r;
            if (gr < M) v = *(const float4*)(A + (long)gr * K + kk + c);
            As[c + 0][r] = v.x; As[c + 1][r] = v.y; As[c + 2][r] = v.z; As[c + 3][r] = v.w;
        }
        #pragma unroll
        for (int i = 0; i < 4; i++) {
            int r = tid / 32 + i * 8;
            int c = (tid % 32) * 4;
            float4 v = *(const float4*)(B + (long)(kk + r) * N + bn + c);
            *(float4*)&Bs[r][c] = v;
        }
        __syncthreads();
        #pragma unroll
        for (int k = 0; k < 32; k++) {
            float a[8], b[8];
            *(float4*)&a[0] = *(const float4*)&As[k][tr];
            *(float4*)&a[4] = *(const float4*)&As[k][tr + 4];
            *(float4*)&b[0] = *(const float4*)&Bs[k][tc];
            *(float4*)&b[4] = *(const float4*)&Bs[k][tc + 4];
            #pragma unroll
            for (int i = 0; i < 8; i++)
                #pragma unroll
                for (int j = 0; j < 8; j++) acc[i][j] += a[i] * b[j];
        }
        __syncthreads();
    }
    #pragma unroll
    for (int i = 0; i < 8; i++) {
        int gr = bm + tr + i;
        if (gr >= M) break;
        #pragma unroll
        for (int j = 0; j < 8; j += 4) {
            float4 v = make_float4(acc[i][j], acc[i][j + 1], acc[i][j + 2], acc[i][j + 3]);
            if (bias) {
                v.x += bias[bn + tc + j + 0];
                v.y += bias[bn + tc + j + 1];
                v.z += bias[bn + tc + j + 2];
                v.w += bias[bn + tc + j + 3];
            }
            *(float4*)(C + (long)gr * N + bn + tc + j) = v;
        }
    }
}

/* ---------------- LayerNorm + FiLM ---------------- */
__global__ void k_ln_film(const float* __restrict__ ls, const float* __restrict__ lb,
                          const float* __restrict__ gam, const float* __restrict__ bet) {
    int n = (blockIdx.x * blockDim.x + threadIdx.x) >> 5;
    int lane = threadIdx.x & 31;
    if (n >= NN) return;
    float4 v = *(const float4*)(g_h + n * D + lane * 4);
    float mu = wredsum(v.x + v.y + v.z + v.w) * (1.f / 128.f);
    float d0 = v.x - mu, d1 = v.y - mu, d2 = v.z - mu, d3 = v.w - mu;
    float var = wredsum(d0 * d0 + d1 * d1 + d2 * d2 + d3 * d3) * (1.f / 128.f);
    float rs = rsqrtf(var + 1e-5f);
    float4 lsv = *(const float4*)(ls + lane * 4);
    float4 lbv = *(const float4*)(lb + lane * 4);
    float4 gv = *(const float4*)(gam + lane * 4);
    float4 bv = *(const float4*)(bet + lane * 4);
    float4 o;
    o.x = gv.x * (d0 * rs * lsv.x + lbv.x) + bv.x;
    o.y = gv.y * (d1 * rs * lsv.y + lbv.y) + bv.y;
    o.z = gv.z * (d2 * rs * lsv.z + lbv.z) + bv.z;
    o.w = gv.w * (d3 * rs * lsv.w + lbv.w) + bv.w;
    *(float4*)(g_hm + n * D + lane * 4) = o;
}

/* ---------------- per-node attention logits (al_s, al_d) ---------------- */
__global__ void k_als(const float* __restrict__ asrc, const float* __restrict__ adst) {
    int n = (blockIdx.x * blockDim.x + threadIdx.x) >> 5;
    int lane = threadIdx.x & 31;
    if (n >= NN) return;
    #pragma unroll
    for (int h = 0; h < NH; h++) {
        float4 xv = *(const float4*)(g_x + ((long)n * NH + h) * D + lane * 4);
        float4 a = *(const float4*)(asrc + h * D + lane * 4);
        float4 b = *(const float4*)(adst + h * D + lane * 4);
        float ss = wredsum(xv.x * a.x + xv.y * a.y + xv.z * a.z + xv.w * a.w);
        float sd = wredsum(xv.x * b.x + xv.y * b.y + xv.z * b.z + xv.w * b.w);
        if (lane == 0) {
            g_als[n * NH + h] = ss;
            g_ald[n * NH + h] = sd;
        }
    }
}

/* ---------------- edge attention vectors v[h] = We_h @ a_edge[h] ---------------- */
__global__ void k_attvec(const float* __restrict__ We, const float* __restrict__ aedge) {
    int t = threadIdx.x;           /* 128 threads */
    int h = t >> 5, f = t & 31;
    float s = 0.f;
    for (int d = 0; d < D; d++) s += We[f * (NH * D) + h * D + d] * aedge[h * D + d];
    g_v[h * EFD + f] = s;
    __syncthreads();
    if (t < NH) {
        float s2 = 0.f;
        for (int k = 0; k < EFD; k++) s2 += g_eamean[k] * g_v[t * EFD + k];
        g_aleself[t] = s2;
    }
}

/* ---------------- per-edge attention logit al_e ---------------- */
__global__ void k_ale(const float* __restrict__ ea) {
    __shared__ float sv[NH * EFD];
    __shared__ float ss[NH];
    __shared__ float se[128 * 33];
    int t = threadIdx.x;           /* 128 */
    long base = (long)blockIdx.x * 128;
    sv[t] = g_v[t];
    if (t < NH) ss[t] = g_aleself[t];
    #pragma unroll
    for (int i = 0; i < 32; i++) {
        long li = (long)t + (long)i * 128;
        long gi = base * EFD + li;
        if (gi < (long)NE * EFD) {
            int row = (int)(li >> 5), col = (int)(li & 31);
            se[row * 33 + col] = ea[gi];
        }
    }
    __syncthreads();
    long j = base + t;
    if (j >= NEF) return;
    if (j < NE) {
        float s0 = 0.f, s1 = 0.f, s2 = 0.f, s3 = 0.f;
        #pragma unroll
        for (int k = 0; k < EFD; k++) {
            float e = se[t * 33 + k];
            s0 += e * sv[k];
            s1 += e * sv[EFD + k];
            s2 += e * sv[2 * EFD + k];
            s3 += e * sv[3 * EFD + k];
        }
        float* o = g_ale + j * NH;
        o[0] = s0; o[1] = s1; o[2] = s2; o[3] = s3;
    } else {
        float* o = g_ale + j * NH;
        o[0] = ss[0]; o[1] = ss[1]; o[2] = ss[2]; o[3] = ss[3];
    }
}

/* ---------------- GAT message passing: warp per destination node ---------------- */
__global__ void k_message(const float* __restrict__ bias) {
    int n = (blockIdx.x * blockDim.x + threadIdx.x) >> 5;
    int lane = threadIdx.x & 31;
    if (n >= NN) return;
    int hh = lane >> 3;
    int dp = (lane & 7) * 16;
    int rb = g_rowptr[n], re = g_rowptr[n + 1];
    float4 ad = *(const float4*)(g_ald + n * NH);

    /* pass A: per-head max */
    float m0 = -1e30f, m1 = -1e30f, m2 = -1e30f, m3 = -1e30f;
    for (int i = rb + lane; i < re; i += 32) {
        int s = g_csrsrc[i], e = g_csreid[i];
        float4 as = *(const float4*)(g_als + s * NH);
        float4 ae = *(const float4*)(g_ale + (long)e * NH);
        float l0 = as.x + ad.x + ae.x; l0 = l0 > 0.f ? l0 : 0.2f * l0; m0 = fmaxf(m0, l0);
        float l1 = as.y + ad.y + ae.y; l1 = l1 > 0.f ? l1 : 0.2f * l1; m1 = fmaxf(m1, l1);
        float l2 = as.z + ad.z + ae.z; l2 = l2 > 0.f ? l2 : 0.2f * l2; m2 = fmaxf(m2, l2);
        float l3 = as.w + ad.w + ae.w; l3 = l3 > 0.f ? l3 : 0.2f * l3; m3 = fmaxf(m3, l3);
    }
    m0 = wredmax(m0); m1 = wredmax(m1); m2 = wredmax(m2); m3 = wredmax(m3);
    float mh = (hh == 0) ? m0 : (hh == 1) ? m1 : (hh == 2) ? m2 : m3;
    float adh = (hh == 0) ? ad.x : (hh == 1) ? ad.y : (hh == 2) ? ad.z : ad.w;

    /* pass B: exp-weighted accumulate */
    float acc[16];
    #pragma unroll
    for (int k = 0; k < 16; k++) acc[k] = 0.f;
    float den = 0.f;
    for (int i = rb; i < re; i++) {
        int s = g_csrsrc[i], e = g_csreid[i];
        float a = g_als[s * NH + hh] + adh + g_ale[(long)e * NH + hh];
        a = a > 0.f ? a : 0.2f * a;
        float w = __expf(a - mh);
        den += w;
        const float* xp = g_x + ((long)s * NH + hh) * D + dp;
        #pragma unroll
        for (int k = 0; k < 4; k++) {
            float4 xv = *(const float4*)(xp + k * 4);
            acc[k * 4 + 0] += w * xv.x;
            acc[k * 4 + 1] += w * xv.y;
            acc[k * 4 + 2] += w * xv.z;
            acc[k * 4 + 3] += w * xv.w;
        }
    }
    float inv = 1.f / (den + 1e-16f);
    #pragma unroll
    for (int k = 0; k < 16; k++) {
        float vv = acc[k] * inv;
        vv += __shfl_xor_sync(0xffffffffu, vv, 8);
        vv += __shfl_xor_sync(0xffffffffu, vv, 16);
        acc[k] = vv * 0.25f;
    }
    if (lane < 8) {
        #pragma unroll
        for (int k = 0; k < 4; k++) {
            float4 o;
            o.x = fmaxf(acc[k * 4 + 0] + bias[dp + k * 4 + 0], 0.f);
            o.y = fmaxf(acc[k * 4 + 1] + bias[dp + k * 4 + 1], 0.f);
            o.z = fmaxf(acc[k * 4 + 2] + bias[dp + k * 4 + 2], 0.f);
            o.w = fmaxf(acc[k * 4 + 3] + bias[dp + k * 4 + 3], 0.f);
            *(float4*)(g_h + n * D + dp + k * 4) = o;
        }
    }
}

/* ---------------- edge head: logit = relu(t[s]+u[d]+p[e]+b1) . W2 + b2 ---------- */
__global__ void k_edge_head(const int* __restrict__ src, const int* __restrict__ dst,
                            const float* __restrict__ b1, const float* __restrict__ W2,
                            const float* __restrict__ b2, float* __restrict__ out) {
    int e = (blockIdx.x * blockDim.x + threadIdx.x) >> 5;
    int lane = threadIdx.x & 31;
    if (e >= NE) return;
    int s = src[e], d = dst[e];
    float4 tv = *(const float4*)(g_t + (long)s * D + lane * 4);
    float4 uv = *(const float4*)(g_u + (long)d * D + lane * 4);
    float4 pv = *(const float4*)(g_p + (long)e * D + lane * 4);
    float4 bv = *(const float4*)(b1 + lane * 4);
    float4 wv = *(const float4*)(W2 + lane * 4);
    float z0 = fmaxf(tv.x + uv.x + pv.x + bv.x, 0.f);
    float z1 = fmaxf(tv.y + uv.y + pv.y + bv.y, 0.f);
    float z2 = fmaxf(tv.z + uv.z + pv.z + bv.z, 0.f);
    float z3 = fmaxf(tv.w + uv.w + pv.w + bv.w, 0.f);
    float s4 = wredsum(z0 * wv.x + z1 * wv.y + z2 * wv.z + z3 * wv.w);
    if (lane == 0) out[e] = s4 + b2[0];
}

/* ---------------- host orchestration ---------------- */
extern "C" void kernel_launch(void* const* d_in, const int* in_sizes, int n_in,
                              void* d_out, int out_size) {
    const float* x      = (const float*)d_in[0];
    const int*   ei     = (const int*)  d_in[1];
    const float* ea     = (const float*)d_in[2];
    const float* gamma  = (const float*)d_in[3];
    const float* beta   = (const float*)d_in[4];
    const float* embW   = (const float*)d_in[5];
    const float* embb   = (const float*)d_in[6];
    const float* lns    = (const float*)d_in[7];
    const float* lnb    = (const float*)d_in[8];
    const float* gatW   = (const float*)d_in[9];
    const float* asrc   = (const float*)d_in[10];
    const float* adst   = (const float*)d_in[11];
    const float* gWe    = (const float*)d_in[12];
    const float* aedge  = (const float*)d_in[13];
    const float* gbias  = (const float*)d_in[14];
    const float* W1     = (const float*)d_in[15];
    const float* b1     = (const float*)d_in[16];
    const float* W2     = (const float*)d_in[17];
    const float* b2     = (const float*)d_in[18];
    float* out = (float*)d_out;

    const int* src = ei;
    const int* dst = ei + NE;

    float *p_h, *p_hm, *p_x, *p_t, *p_u, *p_p;
    cudaGetSymbolAddress((void**)&p_h,  g_h);
    cudaGetSymbolAddress((void**)&p_hm, g_hm);
    cudaGetSymbolAddress((void**)&p_x,  g_x);
    cudaGetSymbolAddress((void**)&p_t,  g_t);
    cudaGetSymbolAddress((void**)&p_u,  g_u);
    cudaGetSymbolAddress((void**)&p_p,  g_p);

    /* edge-attr mean */
    k_eamean1<<<256, 128>>>(ea);
    k_eamean2<<<1, 32>>>();

    /* CSR build */
    k_init_counts<<<(NN + 255) / 256, 256>>>();
    k_count<<<(NE + 255) / 256, 256>>>(dst);
    int nb = (NN + 1023) / 1024;
    k_scan_local<<<nb, 1024>>>();
    k_scan_fixup<<<1, 32>>>(nb);
    k_scan_add<<<(NN + 255) / 256, 256>>>();
    k_scatter_edges<<<(NE + 255) / 256, 256>>>(src, dst);
    k_scatter_self<<<(NN + 255) / 256, 256>>>();

    /* embed: h = x @ embW + embb */
    {
        dim3 grid(1, (NN + 127) / 128);
        k_gemm<<<grid, 256>>>(x, embW, p_h, NN, 128, 128, embb);
    }

    /* layers */
    for (int l = 0; l < NL; l++) {
        k_ln_film<<<(NN * 32 + 255) / 256, 256>>>(lns + l * D, lnb + l * D,
                                                  gamma + l * D, beta + l * D);
        dim3 grid(4, (NN + 127) / 128);   /* N = 512 */
        k_gemm<<<grid, 256>>>(p_hm, gatW + (long)l * D * NH * D, p_x,
                              NN, NH * D, D, (const float*)0);
        k_als<<<(NN * 32 + 255) / 256, 256>>>(asrc + l * NH * D, adst + l * NH * D);
        k_attvec<<<1, 128>>>(gWe + (long)l * EFD * NH * D, aedge + l * NH * D);
        k_ale<<<(NEF + 127) / 128, 128>>>(ea);
        k_message<<<(NN * 32 + 255) / 256, 256>>>(gbias + l * D);
    }

    /* head */
    {
        dim3 grid(1, (NN + 127) / 128);
        k_gemm<<<grid, 256>>>(p_h, W1, p_t, NN, 128, 128, (const float*)0);
        k_gemm<<<grid, 256>>>(p_h, W1 + 128 * 128, p_u, NN, 128, 128, (const float*)0);
        dim3 gridp(1, (NE + 127) / 128);
        k_gemm<<<gridp, 256>>>(ea, W1 + 256 * 128, p_p, NE, 128, 32, (const float*)0);
        k_edge_head<<<(NE * 32 + 255) / 256, 256>>>(src, dst, b1, W2, b2, out);
    }
}

// round 2
// speedup vs baseline: 1.4567x; 1.4567x over previous
#include <cuda_runtime.h>
#include <cuda_fp16.h>

#define NN  25000
#define NE  400000
#define NEF 425000   /* NE + NN self-loops */
#define D   128
#define NH  4
#define EFD 32
#define NL  6

/* ---------------- scratch (static device globals; no allocs) -------------- */
__device__ __align__(16) float  g_h[NN * D];
__device__ __align__(16) float  g_hm[NN * D];
__device__ __align__(16) __half g_x[NN * NH * D];
__device__ __align__(16) float  g_als[NN * NH];
__device__ __align__(16) float  g_ald[NN * NH];
__device__ __align__(16) float  g_ale[NL * NE * NH];    /* all layers, edge order */
__device__ __align__(16) float  g_lg[NEF * NH];         /* per-layer CSR-order logits */
__device__ int   g_rowptr[NN + 1];
__device__ int   g_counts[NN];
__device__ int   g_fill[NN];
__device__ int   g_csrsrc[NEF];
__device__ int   g_csrdst[NEF];
__device__ int   g_csreid[NEF];
__device__ __align__(16) float g_eamean[EFD];
__device__ __align__(16) float g_partial[256 * EFD];
__device__ __align__(16) float g_v[NL * NH * EFD];
__device__ __align__(16) float g_aleself[NL * NH];
__device__ __align__(16) float g_t[NN * D];
__device__ __align__(16) float g_u[NN * D];
__device__ int   g_bsums[32];

/* ---------------- helpers ---------------- */
__device__ __forceinline__ float wredsum(float v) {
    #pragma unroll
    for (int o = 16; o; o >>= 1) v += __shfl_xor_sync(0xffffffffu, v, o);
    return v;
}

/* ---------------- edge-attr mean (deterministic 2-stage) ---------------- */
__global__ void k_eamean1(const float* __restrict__ ea) {
    const int SPAN = 1563;
    int blk = blockIdx.x;
    int w = threadIdx.x >> 5, lane = threadIdx.x & 31;
    long start = (long)blk * SPAN;
    long end = start + SPAN; if (end > NE) end = NE;
    float s = 0.f;
    for (long e = start + w; e < end; e += 4) s += ea[e * EFD + lane];
    __shared__ float sm[4][32];
    sm[w][lane] = s;
    __syncthreads();
    if (w == 0) {
        float t = sm[0][lane] + sm[1][lane] + sm[2][lane] + sm[3][lane];
        g_partial[blk * 32 + lane] = t;
    }
}
__global__ void k_eamean2() {
    int lane = threadIdx.x;
    float s = 0.f;
    for (int b = 0; b < 256; b++) s += g_partial[b * 32 + lane];
    g_eamean[lane] = s * (1.f / (float)NE);
}

/* ---------------- CSR build ---------------- */
__global__ void k_init_counts() {
    int i = blockIdx.x * blockDim.x + threadIdx.x;
    if (i < NN) g_counts[i] = 1;   /* self loop */
}
__global__ void k_count(const int* __restrict__ dst) {
    int e = blockIdx.x * blockDim.x + threadIdx.x;
    if (e < NE) atomicAdd(&g_counts[dst[e]], 1);
}
__global__ void k_scan_local() {
    __shared__ int sm[1024];
    int base = blockIdx.x * 1024;
    int t = threadIdx.x;
    int v = (base + t < NN) ? g_counts[base + t] : 0;
    sm[t] = v;
    __syncthreads();
    #pragma unroll
    for (int off = 1; off < 1024; off <<= 1) {
        int x = (t >= off) ? sm[t - off] : 0;
        __syncthreads();
        sm[t] += x;
        __syncthreads();
    }
    if (base + t < NN) g_rowptr[base + t] = sm[t] - v;   /* exclusive */
    if (t == 1023) g_bsums[blockIdx.x] = sm[1023];
}
__global__ void k_scan_fixup(int nb) {
    if (threadIdx.x == 0) {
        int run = 0;
        for (int b = 0; b < nb; b++) { int t = g_bsums[b]; g_bsums[b] = run; run += t; }
        g_rowptr[NN] = run;
    }
}
__global__ void k_scan_add() {
    int i = blockIdx.x * blockDim.x + threadIdx.x;
    if (i < NN) {
        int r = g_rowptr[i] + g_bsums[i >> 10];
        g_rowptr[i] = r;
        g_fill[i] = r;
    }
}
__global__ void k_scatter_edges(const int* __restrict__ src, const int* __restrict__ dst) {
    int e = blockIdx.x * blockDim.x + threadIdx.x;
    if (e < NE) {
        int d = dst[e];
        int pos = atomicAdd(&g_fill[d], 1);
        g_csrsrc[pos] = src[e];
        g_csrdst[pos] = d;
        g_csreid[pos] = e;
    }
}
__global__ void k_scatter_self() {
    int i = blockIdx.x * blockDim.x + threadIdx.x;
    if (i < NN) {
        int pos = atomicAdd(&g_fill[i], 1);
        g_csrsrc[pos] = i;
        g_csrdst[pos] = i;
        g_csreid[pos] = NE + i;
    }
}

/* ---------------- fp32 GEMM, double-buffered, BK=16 ---------------- */
__device__ __forceinline__ void store8(float* C, long off, const float* v,
                                       const float* bias, int bc) {
    float4 o0, o1;
    o0.x = v[0]; o0.y = v[1]; o0.z = v[2]; o0.w = v[3];
    o1.x = v[4]; o1.y = v[5]; o1.z = v[6]; o1.w = v[7];
    if (bias) {
        o0.x += bias[bc + 0]; o0.y += bias[bc + 1]; o0.z += bias[bc + 2]; o0.w += bias[bc + 3];
        o1.x += bias[bc + 4]; o1.y += bias[bc + 5]; o1.z += bias[bc + 6]; o1.w += bias[bc + 7];
    }
    *(float4*)(C + off) = o0;
    *(float4*)(C + off + 4) = o1;
}
__device__ __forceinline__ void store8(__half* C, long off, const float* v,
                                       const float* bias, int bc) {
    __half hv[8];
    #pragma unroll
    for (int j = 0; j < 8; j++) {
        float t = v[j];
        if (bias) t += bias[bc + j];
        hv[j] = __float2half_rn(t);
    }
    *(uint4*)(C + off) = *(const uint4*)hv;
}

template <typename OutT>
__global__ void __launch_bounds__(256, 2)
k_gemm(const float* __restrict__ A, const float* __restrict__ B,
       OutT* __restrict__ C, int M, int N, int K, const float* __restrict__ bias) {
    __shared__ float As[2][16][128];
    __shared__ float Bs[2][16][128];
    const int bm = blockIdx.y * 128;
    const int bn = blockIdx.x * 128;
    const int tid = threadIdx.x;
    const int tr = (tid >> 4) << 3;
    const int tc = (tid & 15) << 3;
    const int ra = tid >> 1;
    const int ca = (tid & 1) << 3;
    const int rb = tid >> 4;
    const int cb = (tid & 15) << 3;

    float4 a0, a1, b0, b1;
    const int gr_a = bm + ra;

    if (gr_a < M) {
        a0 = *(const float4*)(A + (long)gr_a * K + ca);
        a1 = *(const float4*)(A + (long)gr_a * K + ca + 4);
    } else { a0 = make_float4(0.f,0.f,0.f,0.f); a1 = a0; }
    b0 = *(const float4*)(B + (long)rb * N + bn + cb);
    b1 = *(const float4*)(B + (long)rb * N + bn + cb + 4);

    As[0][ca+0][ra] = a0.x; As[0][ca+1][ra] = a0.y; As[0][ca+2][ra] = a0.z; As[0][ca+3][ra] = a0.w;
    As[0][ca+4][ra] = a1.x; As[0][ca+5][ra] = a1.y; As[0][ca+6][ra] = a1.z; As[0][ca+7][ra] = a1.w;
    *(float4*)&Bs[0][rb][cb] = b0;
    *(float4*)&Bs[0][rb][cb+4] = b1;
    __syncthreads();

    float acc[8][8];
    #pragma unroll
    for (int i = 0; i < 8; i++)
        #pragma unroll
        for (int j = 0; j < 8; j++) acc[i][j] = 0.f;

    const int NT = K >> 4;
    for (int it = 0; it < NT; ++it) {
        if (it + 1 < NT) {
            int kk = (it + 1) << 4;
            if (gr_a < M) {
                a0 = *(const float4*)(A + (long)gr_a * K + kk + ca);
                a1 = *(const float4*)(A + (long)gr_a * K + kk + ca + 4);
            } else { a0 = make_float4(0.f,0.f,0.f,0.f); a1 = a0; }
            b0 = *(const float4*)(B + (long)(kk + rb) * N + bn + cb);
            b1 = *(const float4*)(B + (long)(kk + rb) * N + bn + cb + 4);
        }
        const int st = it & 1;
        #pragma unroll
        for (int k = 0; k < 16; k++) {
            float av[8], bv[8];
            *(float4*)&av[0] = *(const float4*)&As[st][k][tr];
            *(float4*)&av[4] = *(const float4*)&As[st][k][tr + 4];
            *(float4*)&bv[0] = *(const float4*)&Bs[st][k][tc];
            *(float4*)&bv[4] = *(const float4*)&Bs[st][k][tc + 4];
            #pragma unroll
            for (int i = 0; i < 8; i++)
                #pragma unroll
                for (int j = 0; j < 8; j++) acc[i][j] += av[i] * bv[j];
        }
        if (it + 1 < NT) {
            __syncthreads();
            const int sn = (it + 1) & 1;
            As[sn][ca+0][ra] = a0.x; As[sn][ca+1][ra] = a0.y; As[sn][ca+2][ra] = a0.z; As[sn][ca+3][ra] = a0.w;
            As[sn][ca+4][ra] = a1.x; As[sn][ca+5][ra] = a1.y; As[sn][ca+6][ra] = a1.z; As[sn][ca+7][ra] = a1.w;
            *(float4*)&Bs[sn][rb][cb] = b0;
            *(float4*)&Bs[sn][rb][cb+4] = b1;
            __syncthreads();
        }
    }

    #pragma unroll
    for (int i = 0; i < 8; i++) {
        int gr = bm + tr + i;
        if (gr >= M) break;
        store8(C, (long)gr * N + bn + tc, acc[i], bias, bn + tc);
    }
}

/* ---------------- LayerNorm + FiLM ---------------- */
__global__ void k_ln_film(const float* __restrict__ ls, const float* __restrict__ lb,
                          const float* __restrict__ gam, const float* __restrict__ bet) {
    int n = (blockIdx.x * blockDim.x + threadIdx.x) >> 5;
    int lane = threadIdx.x & 31;
    if (n >= NN) return;
    float4 v = *(const float4*)(g_h + n * D + lane * 4);
    float mu = wredsum(v.x + v.y + v.z + v.w) * (1.f / 128.f);
    float d0 = v.x - mu, d1 = v.y - mu, d2 = v.z - mu, d3 = v.w - mu;
    float var = wredsum(d0 * d0 + d1 * d1 + d2 * d2 + d3 * d3) * (1.f / 128.f);
    float rs = rsqrtf(var + 1e-5f);
    float4 lsv = *(const float4*)(ls + lane * 4);
    float4 lbv = *(const float4*)(lb + lane * 4);
    float4 gv = *(const float4*)(gam + lane * 4);
    float4 bv = *(const float4*)(bet + lane * 4);
    float4 o;
    o.x = gv.x * (d0 * rs * lsv.x + lbv.x) + bv.x;
    o.y = gv.y * (d1 * rs * lsv.y + lbv.y) + bv.y;
    o.z = gv.z * (d2 * rs * lsv.z + lbv.z) + bv.z;
    o.w = gv.w * (d3 * rs * lsv.w + lbv.w) + bv.w;
    *(float4*)(g_hm + n * D + lane * 4) = o;
}

/* ---------------- per-node attention logits from fp16 x ---------------- */
__global__ void k_als(const float* __restrict__ asrc, const float* __restrict__ adst) {
    int n = (blockIdx.x * blockDim.x + threadIdx.x) >> 5;
    int lane = threadIdx.x & 31;
    if (n >= NN) return;
    #pragma unroll
    for (int h = 0; h < NH; h++) {
        const __half* xp = g_x + ((long)n * NH + h) * D + lane * 4;
        uint2 r = *(const uint2*)xp;
        float2 f0 = __half22float2(*(__half2*)&r.x);
        float2 f1 = __half22float2(*(__half2*)&r.y);
        float4 a = *(const float4*)(asrc + h * D + lane * 4);
        float4 b = *(const float4*)(adst + h * D + lane * 4);
        float ss = wredsum(f0.x * a.x + f0.y * a.y + f1.x * a.z + f1.y * a.w);
        float sd = wredsum(f0.x * b.x + f0.y * b.y + f1.x * b.z + f1.y * b.w);
        if (lane == 0) {
            g_als[n * NH + h] = ss;
            g_ald[n * NH + h] = sd;
        }
    }
}

/* ---------------- edge attention vectors, all layers ---------------- */
__global__ void k_attvec(const float* __restrict__ gWe, const float* __restrict__ gaedge) {
    int l = blockIdx.x;
    const float* We = gWe + (long)l * EFD * NH * D;
    const float* aedge = gaedge + (long)l * NH * D;
    __shared__ float sv[NH * EFD];
    int t = threadIdx.x;           /* 128 threads */
    int h = t >> 5, f = t & 31;
    float s = 0.f;
    for (int d = 0; d < D; d++) s += We[f * (NH * D) + h * D + d] * aedge[h * D + d];
    sv[h * EFD + f] = s;
    g_v[l * NH * EFD + h * EFD + f] = s;
    __syncthreads();
    if (t < NH) {
        float s2 = 0.f;
        for (int k = 0; k < EFD; k++) s2 += g_eamean[k] * sv[t * EFD + k];
        g_aleself[l * NH + t] = s2;
    }
}

/* ---------------- per-edge attention logit al_e for ALL layers -------------- */
__global__ void k_ale_all(const float* __restrict__ ea) {
    __shared__ float sv[NL * NH * EFD];   /* 768 floats */
    __shared__ float se[128 * 33];
    int t = threadIdx.x;           /* 128 */
    long base = (long)blockIdx.x * 128;
    for (int i = t; i < NL * NH * EFD; i += 128) sv[i] = g_v[i];
    #pragma unroll
    for (int i = 0; i < 32; i++) {
        long li = (long)t + (long)i * 128;
        long gi = base * EFD + li;
        if (gi < (long)NE * EFD) {
            int row = (int)(li >> 5), col = (int)(li & 31);
            se[row * 33 + col] = ea[gi];
        }
    }
    __syncthreads();
    long j = base + t;
    if (j >= NE) return;
    float ev[EFD];
    #pragma unroll
    for (int k = 0; k < EFD; k++) ev[k] = se[t * 33 + k];
    #pragma unroll
    for (int l = 0; l < NL; l++) {
        float s0 = 0.f, s1 = 0.f, s2 = 0.f, s3 = 0.f;
        const float* v = sv + l * NH * EFD;
        #pragma unroll
        for (int k = 0; k < EFD; k++) {
            float e = ev[k];
            s0 += e * v[k];
            s1 += e * v[EFD + k];
            s2 += e * v[2 * EFD + k];
            s3 += e * v[3 * EFD + k];
        }
        float* o = g_ale + ((long)l * NE + j) * NH;
        o[0] = s0; o[1] = s1; o[2] = s2; o[3] = s3;
    }
}

/* ---------------- CSR-order per-edge logits (leaky-relu applied) ------------ */
__global__ void k_logit(const float* __restrict__ ale_l, const float* __restrict__ aleself_l) {
    int i = blockIdx.x * blockDim.x + threadIdx.x;
    if (i >= NEF) return;
    int s = g_csrsrc[i], d = g_csrdst[i], e = g_csreid[i];
    float4 as = *(const float4*)(g_als + (long)s * NH);
    float4 ad = *(const float4*)(g_ald + (long)d * NH);
    float4 ae;
    if (e < NE) ae = *(const float4*)(ale_l + (long)e * NH);
    else        ae = *(const float4*)aleself_l;
    float4 o;
    float a;
    a = as.x + ad.x + ae.x; o.x = a > 0.f ? a : 0.2f * a;
    a = as.y + ad.y + ae.y; o.y = a > 0.f ? a : 0.2f * a;
    a = as.z + ad.z + ae.z; o.z = a > 0.f ? a : 0.2f * a;
    a = as.w + ad.w + ae.w; o.w = a > 0.f ? a : 0.2f * a;
    *(float4*)(g_lg + (long)i * NH) = o;
}

/* ---------------- GAT message passing: warp/node, online softmax ------------ */
__global__ void k_message(const float* __restrict__ bias) {
    int n = (blockIdx.x * blockDim.x + threadIdx.x) >> 5;
    int lane = threadIdx.x & 31;
    if (n >= NN) return;
    int hh = lane >> 3;
    int dp = (lane & 7) << 4;
    int rb = g_rowptr[n], re = g_rowptr[n + 1];

    float acc[16];
    #pragma unroll
    for (int k = 0; k < 16; k++) acc[k] = 0.f;
    float mrun = -1e30f, den = 0.f;

    for (int i = rb; i < re; i++) {
        int s = g_csrsrc[i];
        float4 lg = *(const float4*)(g_lg + (long)i * NH);
        float a = (hh == 0) ? lg.x : (hh == 1) ? lg.y : (hh == 2) ? lg.z : lg.w;
        float mnew = fmaxf(mrun, a);
        float corr = __expf(mrun - mnew);
        float w = __expf(a - mnew);
        mrun = mnew;
        den = den * corr + w;
        const __half* xp = g_x + (((long)s * NH + hh) << 7) + dp;
        uint4 r0 = *(const uint4*)xp;
        uint4 r1 = *(const uint4*)(xp + 8);
        const __half2* hp0 = (const __half2*)&r0;
        const __half2* hp1 = (const __half2*)&r1;
        #pragma unroll
        for (int q = 0; q < 4; q++) {
            float2 f = __half22float2(hp0[q]);
            acc[q * 2 + 0] = acc[q * 2 + 0] * corr + w * f.x;
            acc[q * 2 + 1] = acc[q * 2 + 1] * corr + w * f.y;
        }
        #pragma unroll
        for (int q = 0; q < 4; q++) {
            float2 f = __half22float2(hp1[q]);
            acc[8 + q * 2 + 0] = acc[8 + q * 2 + 0] * corr + w * f.x;
            acc[8 + q * 2 + 1] = acc[8 + q * 2 + 1] * corr + w * f.y;
        }
    }
    float inv = 1.f / (den + 1e-16f);
    #pragma unroll
    for (int k = 0; k < 16; k++) {
        float vv = acc[k] * inv;
        vv += __shfl_xor_sync(0xffffffffu, vv, 8);
        vv += __shfl_xor_sync(0xffffffffu, vv, 16);
        acc[k] = vv * 0.25f;
    }
    if (lane < 8) {
        #pragma unroll
        for (int k = 0; k < 4; k++) {
            float4 o;
            o.x = fmaxf(acc[k * 4 + 0] + bias[dp + k * 4 + 0], 0.f);
            o.y = fmaxf(acc[k * 4 + 1] + bias[dp + k * 4 + 1], 0.f);
            o.z = fmaxf(acc[k * 4 + 2] + bias[dp + k * 4 + 2], 0.f);
            o.w = fmaxf(acc[k * 4 + 3] + bias[dp + k * 4 + 3], 0.f);
            *(float4*)(g_h + n * D + dp + k * 4) = o;
        }
    }
}

/* ---------------- fused edge head ---------------- */
__global__ void __launch_bounds__(256)
k_edge_head(const int* __restrict__ src, const int* __restrict__ dst,
            const float* __restrict__ W1, const float* __restrict__ b1,
            const float* __restrict__ W2, const float* __restrict__ b2,
            const float* __restrict__ ea, float* __restrict__ out) {
    __shared__ float sW[EFD][128];
    __shared__ float sb[128], sw2[128];
    int tid = threadIdx.x;
    for (int i = tid; i < EFD * 128; i += 256) sW[i >> 7][i & 127] = W1[256 * 128 + i];
    if (tid < 128) { sb[tid] = b1[tid]; sw2[tid] = W2[tid]; }
    __syncthreads();
    float bias2 = b2[0];
    int lane = tid & 31;
    int warp = blockIdx.x * 8 + (tid >> 5);
    int nwarps = gridDim.x * 8;
    const int NG = NE / 4;
    for (int g = warp; g < NG; g += nwarps) {
        int e = g * 4;
        float ev[4];
        float4 tu[4];
        #pragma unroll
        for (int k = 0; k < 4; k++) {
            int s = src[e + k], d = dst[e + k];
            ev[k] = ea[(long)(e + k) * EFD + lane];
            float4 tv = *(const float4*)(g_t + (long)s * D + lane * 4);
            float4 uv = *(const float4*)(g_u + (long)d * D + lane * 4);
            tu[k].x = tv.x + uv.x; tu[k].y = tv.y + uv.y;
            tu[k].z = tv.z + uv.z; tu[k].w = tv.w + uv.w;
        }
        float4 p[4];
        #pragma unroll
        for (int k = 0; k < 4; k++) p[k] = make_float4(0.f, 0.f, 0.f, 0.f);
        #pragma unroll
        for (int j = 0; j < EFD; j++) {
            float4 w = *(const float4*)&sW[j][lane * 4];
            #pragma unroll
            for (int k = 0; k < 4; k++) {
                float bj = __shfl_sync(0xffffffffu, ev[k], j);
                p[k].x += bj * w.x; p[k].y += bj * w.y;
                p[k].z += bj * w.z; p[k].w += bj * w.w;
            }
        }
        float4 bb = *(const float4*)&sb[lane * 4];
        float4 w2 = *(const float4*)&sw2[lane * 4];
        #pragma unroll
        for (int k = 0; k < 4; k++) {
            float z0 = fmaxf(tu[k].x + p[k].x + bb.x, 0.f);
            float z1 = fmaxf(tu[k].y + p[k].y + bb.y, 0.f);
            float z2 = fmaxf(tu[k].z + p[k].z + bb.z, 0.f);
            float z3 = fmaxf(tu[k].w + p[k].w + bb.w, 0.f);
            float s4 = wredsum(z0 * w2.x + z1 * w2.y + z2 * w2.z + z3 * w2.w);
            if (lane == 0) out[e + k] = s4 + bias2;
        }
    }
}

/* ---------------- host orchestration ---------------- */
extern "C" void kernel_launch(void* const* d_in, const int* in_sizes, int n_in,
                              void* d_out, int out_size) {
    const float* x      = (const float*)d_in[0];
    const int*   ei     = (const int*)  d_in[1];
    const float* ea     = (const float*)d_in[2];
    const float* gamma  = (const float*)d_in[3];
    const float* beta   = (const float*)d_in[4];
    const float* embW   = (const float*)d_in[5];
    const float* embb   = (const float*)d_in[6];
    const float* lns    = (const float*)d_in[7];
    const float* lnb    = (const float*)d_in[8];
    const float* gatW   = (const float*)d_in[9];
    const float* asrc   = (const float*)d_in[10];
    const float* adst   = (const float*)d_in[11];
    const float* gWe    = (const float*)d_in[12];
    const float* aedge  = (const float*)d_in[13];
    const float* gbias  = (const float*)d_in[14];
    const float* W1     = (const float*)d_in[15];
    const float* b1     = (const float*)d_in[16];
    const float* W2     = (const float*)d_in[17];
    const float* b2     = (const float*)d_in[18];
    float* out = (float*)d_out;

    const int* src = ei;
    const int* dst = ei + NE;

    float *p_h, *p_hm, *p_t, *p_u, *p_ale, *p_aleself;
    __half* p_x;
    cudaGetSymbolAddress((void**)&p_h,  g_h);
    cudaGetSymbolAddress((void**)&p_hm, g_hm);
    cudaGetSymbolAddress((void**)&p_x,  g_x);
    cudaGetSymbolAddress((void**)&p_t,  g_t);
    cudaGetSymbolAddress((void**)&p_u,  g_u);
    cudaGetSymbolAddress((void**)&p_ale, g_ale);
    cudaGetSymbolAddress((void**)&p_aleself, g_aleself);

    /* edge-attr mean, per-layer edge attention vectors, all-layer al_e */
    k_eamean1<<<256, 128>>>(ea);
    k_eamean2<<<1, 32>>>();
    k_attvec<<<NL, 128>>>(gWe, aedge);
    k_ale_all<<<(NE + 127) / 128, 128>>>(ea);

    /* CSR build */
    k_init_counts<<<(NN + 255) / 256, 256>>>();
    k_count<<<(NE + 255) / 256, 256>>>(dst);
    int nb = (NN + 1023) / 1024;
    k_scan_local<<<nb, 1024>>>();
    k_scan_fixup<<<1, 32>>>(nb);
    k_scan_add<<<(NN + 255) / 256, 256>>>();
    k_scatter_edges<<<(NE + 255) / 256, 256>>>(src, dst);
    k_scatter_self<<<(NN + 255) / 256, 256>>>();

    /* embed: h = x @ embW + embb */
    {
        dim3 grid(1, (NN + 127) / 128);
        k_gemm<float><<<grid, 256>>>(x, embW, p_h, NN, 128, 128, embb);
    }

    /* layers */
    for (int l = 0; l < NL; l++) {
        k_ln_film<<<(NN * 32 + 255) / 256, 256>>>(lns + l * D, lnb + l * D,
                                                  gamma + l * D, beta + l * D);
        dim3 grid(4, (NN + 127) / 128);   /* N = 512 */
        k_gemm<__half><<<grid, 256>>>(p_hm, gatW + (long)l * D * NH * D, p_x,
                                      NN, NH * D, D, (const float*)0);
        k_als<<<(NN * 32 + 255) / 256, 256>>>(asrc + l * NH * D, adst + l * NH * D);
        k_logit<<<(NEF + 255) / 256, 256>>>(p_ale + (long)l * NE * NH,
                                            p_aleself + l * NH);
        k_message<<<(NN * 32 + 255) / 256, 256>>>(gbias + l * D);
    }

    /* head */
    {
        dim3 grid(1, (NN + 127) / 128);
        k_gemm<float><<<grid, 256>>>(p_h, W1, p_t, NN, 128, 128, (const float*)0);
        k_gemm<float><<<grid, 256>>>(p_h, W1 + 128 * 128, p_u, NN, 128, 128, (const float*)0);
        k_edge_head<<<2048, 256>>>(src, dst, W1, b1, W2, b2, ea, out);
    }
}

// round 3
// speedup vs baseline: 1.8393x; 1.2626x over previous
#include <cuda_runtime.h>
#include <cuda_fp16.h>
#include <mma.h>

using namespace nvcuda;

#define NN  25000
#define NE  400000
#define NEF 425000   /* NE + NN self-loops */
#define D   128
#define NH  4
#define EFD 32
#define NL  6

/* ---------------- scratch (static device globals; no allocs) -------------- */
__device__ __align__(16) float  g_h[NN * D];
__device__ __align__(16) float  g_hm[NN * D];
__device__ __align__(16) __half g_x[NN * NH * D];
__device__ __align__(16) float  g_als[NN * NH];
__device__ __align__(16) float  g_ald[NN * NH];
__device__ __align__(16) float  g_ale[NL * NE * NH];    /* all layers, edge order */
__device__ __align__(16) float  g_lg[NEF * NH];         /* per-layer CSR-order logits */
__device__ int   g_rowptr[NN + 1];
__device__ int   g_counts[NN];
__device__ int   g_fill[NN];
__device__ int   g_csrsrc[NEF];
__device__ int   g_csrdst[NEF];
__device__ int   g_csreid[NEF];
__device__ __align__(16) float g_eamean[EFD];
__device__ __align__(16) float g_partial[256 * EFD];
__device__ __align__(16) float g_v[NL * NH * EFD];
__device__ __align__(16) float g_aleself[NL * NH];
__device__ __align__(16) float g_t[NN * D];
__device__ __align__(16) float g_u[NN * D];
__device__ int   g_bsums[32];

/* ---------------- helpers ---------------- */
__device__ __forceinline__ float wredsum(float v) {
    #pragma unroll
    for (int o = 16; o; o >>= 1) v += __shfl_xor_sync(0xffffffffu, v, o);
    return v;
}

/* ---------------- edge-attr mean (deterministic 2-stage) ---------------- */
__global__ void k_eamean1(const float* __restrict__ ea) {
    const int SPAN = 1563;
    int blk = blockIdx.x;
    int w = threadIdx.x >> 5, lane = threadIdx.x & 31;
    long start = (long)blk * SPAN;
    long end = start + SPAN; if (end > NE) end = NE;
    float s = 0.f;
    for (long e = start + w; e < end; e += 4) s += ea[e * EFD + lane];
    __shared__ float sm[4][32];
    sm[w][lane] = s;
    __syncthreads();
    if (w == 0) {
        float t = sm[0][lane] + sm[1][lane] + sm[2][lane] + sm[3][lane];
        g_partial[blk * 32 + lane] = t;
    }
}
__global__ void k_eamean2() {
    int lane = threadIdx.x;
    float s = 0.f;
    for (int b = 0; b < 256; b++) s += g_partial[b * 32 + lane];
    g_eamean[lane] = s * (1.f / (float)NE);
}

/* ---------------- CSR build ---------------- */
__global__ void k_init_counts() {
    int i = blockIdx.x * blockDim.x + threadIdx.x;
    if (i < NN) g_counts[i] = 1;   /* self loop */
}
__global__ void k_count(const int* __restrict__ dst) {
    int e = blockIdx.x * blockDim.x + threadIdx.x;
    if (e < NE) atomicAdd(&g_counts[dst[e]], 1);
}
__global__ void k_scan_local() {
    __shared__ int sm[1024];
    int base = blockIdx.x * 1024;
    int t = threadIdx.x;
    int v = (base + t < NN) ? g_counts[base + t] : 0;
    sm[t] = v;
    __syncthreads();
    #pragma unroll
    for (int off = 1; off < 1024; off <<= 1) {
        int x = (t >= off) ? sm[t - off] : 0;
        __syncthreads();
        sm[t] += x;
        __syncthreads();
    }
    if (base + t < NN) g_rowptr[base + t] = sm[t] - v;   /* exclusive */
    if (t == 1023) g_bsums[blockIdx.x] = sm[1023];
}
__global__ void k_scan_fixup(int nb) {
    if (threadIdx.x == 0) {
        int run = 0;
        for (int b = 0; b < nb; b++) { int t = g_bsums[b]; g_bsums[b] = run; run += t; }
        g_rowptr[NN] = run;
    }
}
__global__ void k_scan_add() {
    int i = blockIdx.x * blockDim.x + threadIdx.x;
    if (i < NN) {
        int r = g_rowptr[i] + g_bsums[i >> 10];
        g_rowptr[i] = r;
        g_fill[i] = r;
    }
}
__global__ void k_scatter_edges(const int* __restrict__ src, const int* __restrict__ dst) {
    int e = blockIdx.x * blockDim.x + threadIdx.x;
    if (e < NE) {
        int d = dst[e];
        int pos = atomicAdd(&g_fill[d], 1);
        g_csrsrc[pos] = src[e];
        g_csrdst[pos] = d;
        g_csreid[pos] = e;
    }
}
__global__ void k_scatter_self() {
    int i = blockIdx.x * blockDim.x + threadIdx.x;
    if (i < NN) {
        int pos = atomicAdd(&g_fill[i], 1);
        g_csrsrc[pos] = i;
        g_csrdst[pos] = i;
        g_csreid[pos] = NE + i;
    }
}

/* ================= tensor-core GEMM: C[M,N] = A[M,128] @ B[128,N] =========
   fp16 HMMA, fp32 accumulate. fp32 inputs converted to fp16 in the load path.
   BM=128 BN=128 BK=32, 8 warps (4m x 2n), warp tile 32x64 (2x4 wmma frags). */

#define AS_H 5120      /* halves per A stage: 128*40 */
#define BS_H 4352      /* halves per B stage: 32*136 */
#define SMEM_BYTES 37888

__device__ __forceinline__ void cvt_sts(__half* dst, const float4* p) {
    __half2 h[8];
    h[0] = __floats2half2_rn(p[0].x, p[0].y);
    h[1] = __floats2half2_rn(p[0].z, p[0].w);
    h[2] = __floats2half2_rn(p[1].x, p[1].y);
    h[3] = __floats2half2_rn(p[1].z, p[1].w);
    h[4] = __floats2half2_rn(p[2].x, p[2].y);
    h[5] = __floats2half2_rn(p[2].z, p[2].w);
    h[6] = __floats2half2_rn(p[3].x, p[3].y);
    h[7] = __floats2half2_rn(p[3].z, p[3].w);
    *(uint4*)dst       = *(const uint4*)&h[0];
    *(uint4*)(dst + 8) = *(const uint4*)&h[4];
}

template <typename OutT>
__global__ void __launch_bounds__(256)
k_gemm_mma(const float* __restrict__ A, const float* __restrict__ B,
           OutT* __restrict__ C, int M, int N, const float* __restrict__ bias) {
    __shared__ __align__(16) char smem[SMEM_BYTES];
    __half* As = (__half*)smem;                 /* [2][128][40] */
    __half* Bs = (__half*)(smem + 20480);       /* [2][32][136] */
    float*  Cs = (float*)smem;                  /* [128][72] epilogue reuse */

    const int tid = threadIdx.x;
    const int bm = blockIdx.y * 128;
    const int bn = blockIdx.x * 128;
    const int warp = tid >> 5;
    const int wm = warp >> 1;      /* 0..3 */
    const int wn = warp & 1;       /* 0..1 */

    const int r_a = tid >> 1, ca = (tid & 1) * 16;
    const int r_b = tid >> 3, cb = (tid & 7) * 16;
    const bool arow_ok = (bm + r_a) < M;
    const float* Aptr = A + (long)(bm + r_a) * 128 + ca;
    const float* Bptr = B + (long)r_b * N + bn + cb;

    float4 pa[4], pb[4];
    #define LOAD_A(kk) do { \
        if (arow_ok) { \
            pa[0] = *(const float4*)(Aptr + (kk)); \
            pa[1] = *(const float4*)(Aptr + (kk) + 4); \
            pa[2] = *(const float4*)(Aptr + (kk) + 8); \
            pa[3] = *(const float4*)(Aptr + (kk) + 12); \
        } else { pa[0] = pa[1] = pa[2] = pa[3] = make_float4(0.f,0.f,0.f,0.f); } \
    } while (0)
    #define LOAD_B(kk) do { \
        const float* bp = Bptr + (long)(kk) * N; \
        pb[0] = *(const float4*)bp; \
        pb[1] = *(const float4*)(bp + 4); \
        pb[2] = *(const float4*)(bp + 8); \
        pb[3] = *(const float4*)(bp + 12); \
    } while (0)
    #define STS(st) do { \
        cvt_sts(As + (st) * AS_H + r_a * 40 + ca, pa); \
        cvt_sts(Bs + (st) * BS_H + r_b * 136 + cb, pb); \
    } while (0)

    wmma::fragment<wmma::accumulator, 16, 16, 16, float> cf[2][4];
    #pragma unroll
    for (int i = 0; i < 2; i++)
        #pragma unroll
        for (int j = 0; j < 4; j++) wmma::fill_fragment(cf[i][j], 0.f);

    LOAD_A(0); LOAD_B(0);
    STS(0);
    __syncthreads();

    #pragma unroll
    for (int t = 0; t < 4; t++) {
        if (t < 3) { LOAD_A((t + 1) * 32); LOAD_B((t + 1) * 32); }
        const int st = t & 1;
        #pragma unroll
        for (int ks = 0; ks < 2; ks++) {
            wmma::fragment<wmma::matrix_a, 16, 16, 16, __half, wmma::row_major> af0, af1;
            wmma::load_matrix_sync(af0, As + st * AS_H + (wm * 32) * 40 + ks * 16, 40);
            wmma::load_matrix_sync(af1, As + st * AS_H + (wm * 32 + 16) * 40 + ks * 16, 40);
            #pragma unroll
            for (int j = 0; j < 4; j++) {
                wmma::fragment<wmma::matrix_b, 16, 16, 16, __half, wmma::row_major> bf;
                wmma::load_matrix_sync(bf, Bs + st * BS_H + (ks * 16) * 136 + wn * 64 + j * 16, 136);
                wmma::mma_sync(cf[0][j], af0, bf, cf[0][j]);
                wmma::mma_sync(cf[1][j], af1, bf, cf[1][j]);
            }
        }
        if (t < 3) {
            __syncthreads();
            STS((t + 1) & 1);
            __syncthreads();
        }
    }

    /* epilogue: two phases through smem (Cs reuses As/Bs) */
    #pragma unroll
    for (int ph = 0; ph < 2; ph++) {
        __syncthreads();
        #pragma unroll
        for (int i = 0; i < 2; i++)
            #pragma unroll
            for (int q = 0; q < 2; q++)
                wmma::store_matrix_sync(Cs + (wm * 32 + i * 16) * 72 + wn * 32 + q * 16,
                                        cf[i][ph * 2 + q], 72, wmma::mem_row_major);
        __syncthreads();
        int r = tid >> 1;
        int c0 = (tid & 1) * 32;
        int gm = bm + r;
        if (gm < M) {
            const float* srow = Cs + r * 72 + c0;
            int gnb = bn + (c0 ? 64 : 0) + ph * 32;
            #pragma unroll
            for (int c = 0; c < 32; c += 4) {
                float4 v = *(const float4*)(srow + c);
                if (bias) {
                    v.x += bias[gnb + c + 0];
                    v.y += bias[gnb + c + 1];
                    v.z += bias[gnb + c + 2];
                    v.w += bias[gnb + c + 3];
                }
                if (sizeof(OutT) == 4) {
                    *(float4*)((float*)C + (long)gm * N + gnb + c) = v;
                } else {
                    __half2 h0 = __floats2half2_rn(v.x, v.y);
                    __half2 h1 = __floats2half2_rn(v.z, v.w);
                    uint2 u; u.x = *(unsigned*)&h0; u.y = *(unsigned*)&h1;
                    *(uint2*)((__half*)C + (long)gm * N + gnb + c) = u;
                }
            }
        }
    }
    #undef LOAD_A
    #undef LOAD_B
    #undef STS
}

/* ---------------- LayerNorm + FiLM ---------------- */
__global__ void k_ln_film(const float* __restrict__ ls, const float* __restrict__ lb,
                          const float* __restrict__ gam, const float* __restrict__ bet) {
    int n = (blockIdx.x * blockDim.x + threadIdx.x) >> 5;
    int lane = threadIdx.x & 31;
    if (n >= NN) return;
    float4 v = *(const float4*)(g_h + n * D + lane * 4);
    float mu = wredsum(v.x + v.y + v.z + v.w) * (1.f / 128.f);
    float d0 = v.x - mu, d1 = v.y - mu, d2 = v.z - mu, d3 = v.w - mu;
    float var = wredsum(d0 * d0 + d1 * d1 + d2 * d2 + d3 * d3) * (1.f / 128.f);
    float rs = rsqrtf(var + 1e-5f);
    float4 lsv = *(const float4*)(ls + lane * 4);
    float4 lbv = *(const float4*)(lb + lane * 4);
    float4 gv = *(const float4*)(gam + lane * 4);
    float4 bv = *(const float4*)(bet + lane * 4);
    float4 o;
    o.x = gv.x * (d0 * rs * lsv.x + lbv.x) + bv.x;
    o.y = gv.y * (d1 * rs * lsv.y + lbv.y) + bv.y;
    o.z = gv.z * (d2 * rs * lsv.z + lbv.z) + bv.z;
    o.w = gv.w * (d3 * rs * lsv.w + lbv.w) + bv.w;
    *(float4*)(g_hm + n * D + lane * 4) = o;
}

/* ---------------- per-node attention logits from fp16 x ---------------- */
__global__ void k_als(const float* __restrict__ asrc, const float* __restrict__ adst) {
    int n = (blockIdx.x * blockDim.x + threadIdx.x) >> 5;
    int lane = threadIdx.x & 31;
    if (n >= NN) return;
    #pragma unroll
    for (int h = 0; h < NH; h++) {
        const __half* xp = g_x + ((long)n * NH + h) * D + lane * 4;
        uint2 r = *(const uint2*)xp;
        float2 f0 = __half22float2(*(__half2*)&r.x);
        float2 f1 = __half22float2(*(__half2*)&r.y);
        float4 a = *(const float4*)(asrc + h * D + lane * 4);
        float4 b = *(const float4*)(adst + h * D + lane * 4);
        float ss = wredsum(f0.x * a.x + f0.y * a.y + f1.x * a.z + f1.y * a.w);
        float sd = wredsum(f0.x * b.x + f0.y * b.y + f1.x * b.z + f1.y * b.w);
        if (lane == 0) {
            g_als[n * NH + h] = ss;
            g_ald[n * NH + h] = sd;
        }
    }
}

/* ---------------- edge attention vectors, all layers ---------------- */
__global__ void k_attvec(const float* __restrict__ gWe, const float* __restrict__ gaedge) {
    int l = blockIdx.x;
    const float* We = gWe + (long)l * EFD * NH * D;
    const float* aedge = gaedge + (long)l * NH * D;
    __shared__ float sv[NH * EFD];
    int t = threadIdx.x;           /* 128 threads */
    int h = t >> 5, f = t & 31;
    float s = 0.f;
    for (int d = 0; d < D; d++) s += We[f * (NH * D) + h * D + d] * aedge[h * D + d];
    sv[h * EFD + f] = s;
    g_v[l * NH * EFD + h * EFD + f] = s;
    __syncthreads();
    if (t < NH) {
        float s2 = 0.f;
        for (int k = 0; k < EFD; k++) s2 += g_eamean[k] * sv[t * EFD + k];
        g_aleself[l * NH + t] = s2;
    }
}

/* ---------------- per-edge attention logit al_e for ALL layers -------------- */
__global__ void k_ale_all(const float* __restrict__ ea) {
    __shared__ float sv[NL * NH * EFD];   /* 768 floats */
    __shared__ float se[128 * 33];
    int t = threadIdx.x;           /* 128 */
    long base = (long)blockIdx.x * 128;
    for (int i = t; i < NL * NH * EFD; i += 128) sv[i] = g_v[i];
    #pragma unroll
    for (int i = 0; i < 32; i++) {
        long li = (long)t + (long)i * 128;
        long gi = base * EFD + li;
        if (gi < (long)NE * EFD) {
            int row = (int)(li >> 5), col = (int)(li & 31);
            se[row * 33 + col] = ea[gi];
        }
    }
    __syncthreads();
    long j = base + t;
    if (j >= NE) return;
    float ev[EFD];
    #pragma unroll
    for (int k = 0; k < EFD; k++) ev[k] = se[t * 33 + k];
    #pragma unroll
    for (int l = 0; l < NL; l++) {
        float s0 = 0.f, s1 = 0.f, s2 = 0.f, s3 = 0.f;
        const float* v = sv + l * NH * EFD;
        #pragma unroll
        for (int k = 0; k < EFD; k++) {
            float e = ev[k];
            s0 += e * v[k];
            s1 += e * v[EFD + k];
            s2 += e * v[2 * EFD + k];
            s3 += e * v[3 * EFD + k];
        }
        float* o = g_ale + ((long)l * NE + j) * NH;
        o[0] = s0; o[1] = s1; o[2] = s2; o[3] = s3;
    }
}

/* ---------------- CSR-order per-edge logits (leaky-relu applied) ------------ */
__global__ void k_logit(const float* __restrict__ ale_l, const float* __restrict__ aleself_l) {
    int i = blockIdx.x * blockDim.x + threadIdx.x;
    if (i >= NEF) return;
    int s = g_csrsrc[i], d = g_csrdst[i], e = g_csreid[i];
    float4 as = *(const float4*)(g_als + (long)s * NH);
    float4 ad = *(const float4*)(g_ald + (long)d * NH);
    float4 ae;
    if (e < NE) ae = *(const float4*)(ale_l + (long)e * NH);
    else        ae = *(const float4*)aleself_l;
    float4 o;
    float a;
    a = as.x + ad.x + ae.x; o.x = a > 0.f ? a : 0.2f * a;
    a = as.y + ad.y + ae.y; o.y = a > 0.f ? a : 0.2f * a;
    a = as.z + ad.z + ae.z; o.z = a > 0.f ? a : 0.2f * a;
    a = as.w + ad.w + ae.w; o.w = a > 0.f ? a : 0.2f * a;
    *(float4*)(g_lg + (long)i * NH) = o;
}

/* ---------------- GAT message passing: warp/node, online softmax ------------ */
__global__ void k_message(const float* __restrict__ bias) {
    int n = (blockIdx.x * blockDim.x + threadIdx.x) >> 5;
    int lane = threadIdx.x & 31;
    if (n >= NN) return;
    int hh = lane >> 3;
    int dp = (lane & 7) << 4;
    int rb = g_rowptr[n], re = g_rowptr[n + 1];

    float acc[16];
    #pragma unroll
    for (int k = 0; k < 16; k++) acc[k] = 0.f;
    float mrun = -1e30f, den = 0.f;

    for (int i = rb; i < re; i++) {
        int s = g_csrsrc[i];
        float4 lg = *(const float4*)(g_lg + (long)i * NH);
        float a = (hh == 0) ? lg.x : (hh == 1) ? lg.y : (hh == 2) ? lg.z : lg.w;
        float mnew = fmaxf(mrun, a);
        float corr = __expf(mrun - mnew);
        float w = __expf(a - mnew);
        mrun = mnew;
        den = den * corr + w;
        const __half* xp = g_x + (((long)s * NH + hh) << 7) + dp;
        uint4 r0 = *(const uint4*)xp;
        uint4 r1 = *(const uint4*)(xp + 8);
        const __half2* hp0 = (const __half2*)&r0;
        const __half2* hp1 = (const __half2*)&r1;
        #pragma unroll
        for (int q = 0; q < 4; q++) {
            float2 f = __half22float2(hp0[q]);
            acc[q * 2 + 0] = acc[q * 2 + 0] * corr + w * f.x;
            acc[q * 2 + 1] = acc[q * 2 + 1] * corr + w * f.y;
        }
        #pragma unroll
        for (int q = 0; q < 4; q++) {
            float2 f = __half22float2(hp1[q]);
            acc[8 + q * 2 + 0] = acc[8 + q * 2 + 0] * corr + w * f.x;
            acc[8 + q * 2 + 1] = acc[8 + q * 2 + 1] * corr + w * f.y;
        }
    }
    float inv = 1.f / (den + 1e-16f);
    #pragma unroll
    for (int k = 0; k < 16; k++) {
        float vv = acc[k] * inv;
        vv += __shfl_xor_sync(0xffffffffu, vv, 8);
        vv += __shfl_xor_sync(0xffffffffu, vv, 16);
        acc[k] = vv * 0.25f;
    }
    if (lane < 8) {
        #pragma unroll
        for (int k = 0; k < 4; k++) {
            float4 o;
            o.x = fmaxf(acc[k * 4 + 0] + bias[dp + k * 4 + 0], 0.f);
            o.y = fmaxf(acc[k * 4 + 1] + bias[dp + k * 4 + 1], 0.f);
            o.z = fmaxf(acc[k * 4 + 2] + bias[dp + k * 4 + 2], 0.f);
            o.w = fmaxf(acc[k * 4 + 3] + bias[dp + k * 4 + 3], 0.f);
            *(float4*)(g_h + n * D + dp + k * 4) = o;
        }
    }
}

/* ---------------- fused edge head ---------------- */
__global__ void __launch_bounds__(256)
k_edge_head(const int* __restrict__ src, const int* __restrict__ dst,
            const float* __restrict__ W1, const float* __restrict__ b1,
            const float* __restrict__ W2, const float* __restrict__ b2,
            const float* __restrict__ ea, float* __restrict__ out) {
    __shared__ float sW[EFD][128];
    __shared__ float sb[128], sw2[128];
    int tid = threadIdx.x;
    for (int i = tid; i < EFD * 128; i += 256) sW[i >> 7][i & 127] = W1[256 * 128 + i];
    if (tid < 128) { sb[tid] = b1[tid]; sw2[tid] = W2[tid]; }
    __syncthreads();
    float bias2 = b2[0];
    int lane = tid & 31;
    int warp = blockIdx.x * 8 + (tid >> 5);
    int nwarps = gridDim.x * 8;
    const int NG = NE / 4;
    for (int g = warp; g < NG; g += nwarps) {
        int e = g * 4;
        float ev[4];
        float4 tu[4];
        #pragma unroll
        for (int k = 0; k < 4; k++) {
            int s = src[e + k], d = dst[e + k];
            ev[k] = ea[(long)(e + k) * EFD + lane];
            float4 tv = *(const float4*)(g_t + (long)s * D + lane * 4);
            float4 uv = *(const float4*)(g_u + (long)d * D + lane * 4);
            tu[k].x = tv.x + uv.x; tu[k].y = tv.y + uv.y;
            tu[k].z = tv.z + uv.z; tu[k].w = tv.w + uv.w;
        }
        float4 p[4];
        #pragma unroll
        for (int k = 0; k < 4; k++) p[k] = make_float4(0.f, 0.f, 0.f, 0.f);
        #pragma unroll
        for (int j = 0; j < EFD; j++) {
            float4 w = *(const float4*)&sW[j][lane * 4];
            #pragma unroll
            for (int k = 0; k < 4; k++) {
                float bj = __shfl_sync(0xffffffffu, ev[k], j);
                p[k].x += bj * w.x; p[k].y += bj * w.y;
                p[k].z += bj * w.z; p[k].w += bj * w.w;
            }
        }
        float4 bb = *(const float4*)&sb[lane * 4];
        float4 w2 = *(const float4*)&sw2[lane * 4];
        #pragma unroll
        for (int k = 0; k < 4; k++) {
            float z0 = fmaxf(tu[k].x + p[k].x + bb.x, 0.f);
            float z1 = fmaxf(tu[k].y + p[k].y + bb.y, 0.f);
            float z2 = fmaxf(tu[k].z + p[k].z + bb.z, 0.f);
            float z3 = fmaxf(tu[k].w + p[k].w + bb.w, 0.f);
            float s4 = wredsum(z0 * w2.x + z1 * w2.y + z2 * w2.z + z3 * w2.w);
            if (lane == 0) out[e + k] = s4 + bias2;
        }
    }
}

/* ---------------- host orchestration ---------------- */
extern "C" void kernel_launch(void* const* d_in, const int* in_sizes, int n_in,
                              void* d_out, int out_size) {
    const float* x      = (const float*)d_in[0];
    const int*   ei     = (const int*)  d_in[1];
    const float* ea     = (const float*)d_in[2];
    const float* gamma  = (const float*)d_in[3];
    const float* beta   = (const float*)d_in[4];
    const float* embW   = (const float*)d_in[5];
    const float* embb   = (const float*)d_in[6];
    const float* lns    = (const float*)d_in[7];
    const float* lnb    = (const float*)d_in[8];
    const float* gatW   = (const float*)d_in[9];
    const float* asrc   = (const float*)d_in[10];
    const float* adst   = (const float*)d_in[11];
    const float* gWe    = (const float*)d_in[12];
    const float* aedge  = (const float*)d_in[13];
    const float* gbias  = (const float*)d_in[14];
    const float* W1     = (const float*)d_in[15];
    const float* b1     = (const float*)d_in[16];
    const float* W2     = (const float*)d_in[17];
    const float* b2     = (const float*)d_in[18];
    float* out = (float*)d_out;

    const int* src = ei;
    const int* dst = ei + NE;

    float *p_h, *p_hm, *p_t, *p_u, *p_ale, *p_aleself;
    __half* p_x;
    cudaGetSymbolAddress((void**)&p_h,  g_h);
    cudaGetSymbolAddress((void**)&p_hm, g_hm);
    cudaGetSymbolAddress((void**)&p_x,  g_x);
    cudaGetSymbolAddress((void**)&p_t,  g_t);
    cudaGetSymbolAddress((void**)&p_u,  g_u);
    cudaGetSymbolAddress((void**)&p_ale, g_ale);
    cudaGetSymbolAddress((void**)&p_aleself, g_aleself);

    /* edge-attr mean, per-layer edge attention vectors, all-layer al_e */
    k_eamean1<<<256, 128>>>(ea);
    k_eamean2<<<1, 32>>>();
    k_attvec<<<NL, 128>>>(gWe, aedge);
    k_ale_all<<<(NE + 127) / 128, 128>>>(ea);

    /* CSR build */
    k_init_counts<<<(NN + 255) / 256, 256>>>();
    k_count<<<(NE + 255) / 256, 256>>>(dst);
    int nb = (NN + 1023) / 1024;
    k_scan_local<<<nb, 1024>>>();
    k_scan_fixup<<<1, 32>>>(nb);
    k_scan_add<<<(NN + 255) / 256, 256>>>();
    k_scatter_edges<<<(NE + 255) / 256, 256>>>(src, dst);
    k_scatter_self<<<(NN + 255) / 256, 256>>>();

    const int MB = (NN + 127) / 128;   /* 196 */

    /* embed: h = x @ embW + embb */
    k_gemm_mma<float><<<dim3(1, MB), 256>>>(x, embW, p_h, NN, 128, embb);

    /* layers */
    for (int l = 0; l < NL; l++) {
        k_ln_film<<<(NN * 32 + 255) / 256, 256>>>(lns + l * D, lnb + l * D,
                                                  gamma + l * D, beta + l * D);
        k_gemm_mma<__half><<<dim3(4, MB), 256>>>(p_hm, gatW + (long)l * D * NH * D,
                                                 p_x, NN, 512, (const float*)0);
        k_als<<<(NN * 32 + 255) / 256, 256>>>(asrc + l * NH * D, adst + l * NH * D);
        k_logit<<<(NEF + 255) / 256, 256>>>(p_ale + (long)l * NE * NH,
                                            p_aleself + l * NH);
        k_message<<<(NN * 32 + 255) / 256, 256>>>(gbias + l * D);
    }

    /* head */
    k_gemm_mma<float><<<dim3(1, MB), 256>>>(p_h, W1, p_t, NN, 128, (const float*)0);
    k_gemm_mma<float><<<dim3(1, MB), 256>>>(p_h, W1 + 128 * 128, p_u, NN, 128, (const float*)0);
    k_edge_head<<<2048, 256>>>(src, dst, W1, b1, W2, b2, ea, out);
}

// round 4
// speedup vs baseline: 1.8689x; 1.0161x over previous
#include <cuda_runtime.h>
#include <cuda_fp16.h>
#include <mma.h>

using namespace nvcuda;

#define NN  25000
#define NE  400000
#define NEF 425000   /* NE + NN self-loops */
#define D   128
#define NH  4
#define EFD 32
#define NL  6

/* ---------------- scratch (static device globals; no allocs) -------------- */
__device__ __align__(16) float  g_h[NN * D];
__device__ __align__(16) float  g_hm[NN * D];
__device__ __align__(16) __half g_x[NN * NH * D];
__device__ __align__(16) float  g_als[NN * NH];
__device__ __align__(16) float  g_ald[NN * NH];
__device__ __align__(16) float  g_ale[NL * NE * NH];    /* all layers, edge order */
__device__ __align__(16) float  g_lg[NEF * NH];         /* CSR-order normalized weights */
__device__ int   g_rowptr[NN + 1];
__device__ int   g_counts[NN];
__device__ int   g_fill[NN];
__device__ int   g_csrsrc[NEF];
__device__ int   g_csreid[NEF];
__device__ __align__(16) float g_eamean[EFD];
__device__ __align__(16) float g_partial[256 * EFD];
__device__ __align__(16) float g_v[NL * NH * EFD];
__device__ __align__(16) float g_aleself[NL * NH];
__device__ __align__(16) float g_t[NN * D];
__device__ __align__(16) float g_u[NN * D];
__device__ int   g_bsums[32];

/* ---------------- helpers ---------------- */
__device__ __forceinline__ float wredsum(float v) {
    #pragma unroll
    for (int o = 16; o; o >>= 1) v += __shfl_xor_sync(0xffffffffu, v, o);
    return v;
}
__device__ __forceinline__ void wredsum4(float4& v) {
    #pragma unroll
    for (int o = 16; o; o >>= 1) {
        v.x += __shfl_xor_sync(0xffffffffu, v.x, o);
        v.y += __shfl_xor_sync(0xffffffffu, v.y, o);
        v.z += __shfl_xor_sync(0xffffffffu, v.z, o);
        v.w += __shfl_xor_sync(0xffffffffu, v.w, o);
    }
}
__device__ __forceinline__ void wredmax4(float4& v) {
    #pragma unroll
    for (int o = 16; o; o >>= 1) {
        v.x = fmaxf(v.x, __shfl_xor_sync(0xffffffffu, v.x, o));
        v.y = fmaxf(v.y, __shfl_xor_sync(0xffffffffu, v.y, o));
        v.z = fmaxf(v.z, __shfl_xor_sync(0xffffffffu, v.z, o));
        v.w = fmaxf(v.w, __shfl_xor_sync(0xffffffffu, v.w, o));
    }
}

/* ---------------- edge-attr mean (deterministic 2-stage) ---------------- */
__global__ void k_eamean1(const float* __restrict__ ea) {
    const int SPAN = 1563;
    int blk = blockIdx.x;
    int w = threadIdx.x >> 5, lane = threadIdx.x & 31;
    long start = (long)blk * SPAN;
    long end = start + SPAN; if (end > NE) end = NE;
    float s = 0.f;
    for (long e = start + w; e < end; e += 4) s += ea[e * EFD + lane];
    __shared__ float sm[4][32];
    sm[w][lane] = s;
    __syncthreads();
    if (w == 0) {
        float t = sm[0][lane] + sm[1][lane] + sm[2][lane] + sm[3][lane];
        g_partial[blk * 32 + lane] = t;
    }
}
__global__ void k_eamean2() {
    int lane = threadIdx.x;
    float s = 0.f;
    for (int b = 0; b < 256; b++) s += g_partial[b * 32 + lane];
    g_eamean[lane] = s * (1.f / (float)NE);
}

/* ---------------- CSR build ---------------- */
__global__ void k_init_counts() {
    int i = blockIdx.x * blockDim.x + threadIdx.x;
    if (i < NN) g_counts[i] = 1;   /* self loop */
}
__global__ void k_count(const int* __restrict__ dst) {
    int e = blockIdx.x * blockDim.x + threadIdx.x;
    if (e < NE) atomicAdd(&g_counts[dst[e]], 1);
}
__global__ void k_scan_local() {
    __shared__ int sm[1024];
    int base = blockIdx.x * 1024;
    int t = threadIdx.x;
    int v = (base + t < NN) ? g_counts[base + t] : 0;
    sm[t] = v;
    __syncthreads();
    #pragma unroll
    for (int off = 1; off < 1024; off <<= 1) {
        int x = (t >= off) ? sm[t - off] : 0;
        __syncthreads();
        sm[t] += x;
        __syncthreads();
    }
    if (base + t < NN) g_rowptr[base + t] = sm[t] - v;   /* exclusive */
    if (t == 1023) g_bsums[blockIdx.x] = sm[1023];
}
__global__ void k_scan_fixup(int nb) {
    if (threadIdx.x == 0) {
        int run = 0;
        for (int b = 0; b < nb; b++) { int t = g_bsums[b]; g_bsums[b] = run; run += t; }
        g_rowptr[NN] = run;
    }
}
__global__ void k_scan_add() {
    int i = blockIdx.x * blockDim.x + threadIdx.x;
    if (i < NN) {
        int r = g_rowptr[i] + g_bsums[i >> 10];
        g_rowptr[i] = r;
        g_fill[i] = r;
    }
}
__global__ void k_scatter_edges(const int* __restrict__ src, const int* __restrict__ dst) {
    int e = blockIdx.x * blockDim.x + threadIdx.x;
    if (e < NE) {
        int d = dst[e];
        int pos = atomicAdd(&g_fill[d], 1);
        g_csrsrc[pos] = src[e];
        g_csreid[pos] = e;
    }
}
__global__ void k_scatter_self() {
    int i = blockIdx.x * blockDim.x + threadIdx.x;
    if (i < NN) {
        int pos = atomicAdd(&g_fill[i], 1);
        g_csrsrc[pos] = i;
        g_csreid[pos] = NE + i;
    }
}

/* ================= tensor-core GEMM: C[M,N] = A[M,128] @ B[128,N] =========
   fp16 HMMA, fp32 accumulate. Optional fused per-head attention dots:
   when av != null (x-projection GEMM, N=512, one head per n-block), the
   epilogue also computes als/ald = sum_col out*att_{src,dst}[head]. */

#define AS_H 5120      /* halves per A stage: 128*40 */
#define BS_H 4352      /* halves per B stage: 32*136 */
#define SMEM_BYTES 37888

__device__ __forceinline__ void cvt_sts(__half* dst, const float4* p) {
    __half2 h[8];
    h[0] = __floats2half2_rn(p[0].x, p[0].y);
    h[1] = __floats2half2_rn(p[0].z, p[0].w);
    h[2] = __floats2half2_rn(p[1].x, p[1].y);
    h[3] = __floats2half2_rn(p[1].z, p[1].w);
    h[4] = __floats2half2_rn(p[2].x, p[2].y);
    h[5] = __floats2half2_rn(p[2].z, p[2].w);
    h[6] = __floats2half2_rn(p[3].x, p[3].y);
    h[7] = __floats2half2_rn(p[3].z, p[3].w);
    *(uint4*)dst       = *(const uint4*)&h[0];
    *(uint4*)(dst + 8) = *(const uint4*)&h[4];
}

template <typename OutT>
__global__ void __launch_bounds__(256)
k_gemm_mma(const float* __restrict__ A, const float* __restrict__ B,
           OutT* __restrict__ C, int M, int N, const float* __restrict__ bias,
           const float* __restrict__ av, const float* __restrict__ dv,
           float* __restrict__ als_out, float* __restrict__ ald_out) {
    __shared__ __align__(16) char smem[SMEM_BYTES];
    __half* As = (__half*)smem;                 /* [2][128][40] */
    __half* Bs = (__half*)(smem + 20480);       /* [2][32][136] */
    float*  Cs = (float*)smem;                  /* [128][72] epilogue reuse */

    const int tid = threadIdx.x;
    const int bm = blockIdx.y * 128;
    const int bn = blockIdx.x * 128;
    const int warp = tid >> 5;
    const int wm = warp >> 1;      /* 0..3 */
    const int wn = warp & 1;       /* 0..1 */

    const int r_a = tid >> 1, ca = (tid & 1) * 16;
    const int r_b = tid >> 3, cb = (tid & 7) * 16;
    const bool arow_ok = (bm + r_a) < M;
    const float* Aptr = A + (long)(bm + r_a) * 128 + ca;
    const float* Bptr = B + (long)r_b * N + bn + cb;

    float4 pa[4], pb[4];
    #define LOAD_A(kk) do { \
        if (arow_ok) { \
            pa[0] = *(const float4*)(Aptr + (kk)); \
            pa[1] = *(const float4*)(Aptr + (kk) + 4); \
            pa[2] = *(const float4*)(Aptr + (kk) + 8); \
            pa[3] = *(const float4*)(Aptr + (kk) + 12); \
        } else { pa[0] = pa[1] = pa[2] = pa[3] = make_float4(0.f,0.f,0.f,0.f); } \
    } while (0)
    #define LOAD_B(kk) do { \
        const float* bp = Bptr + (long)(kk) * N; \
        pb[0] = *(const float4*)bp; \
        pb[1] = *(const float4*)(bp + 4); \
        pb[2] = *(const float4*)(bp + 8); \
        pb[3] = *(const float4*)(bp + 12); \
    } while (0)
    #define STS(st) do { \
        cvt_sts(As + (st) * AS_H + r_a * 40 + ca, pa); \
        cvt_sts(Bs + (st) * BS_H + r_b * 136 + cb, pb); \
    } while (0)

    wmma::fragment<wmma::accumulator, 16, 16, 16, float> cf[2][4];
    #pragma unroll
    for (int i = 0; i < 2; i++)
        #pragma unroll
        for (int j = 0; j < 4; j++) wmma::fill_fragment(cf[i][j], 0.f);

    LOAD_A(0); LOAD_B(0);
    STS(0);
    __syncthreads();

    #pragma unroll
    for (int t = 0; t < 4; t++) {
        if (t < 3) { LOAD_A((t + 1) * 32); LOAD_B((t + 1) * 32); }
        const int st = t & 1;
        #pragma unroll
        for (int ks = 0; ks < 2; ks++) {
            wmma::fragment<wmma::matrix_a, 16, 16, 16, __half, wmma::row_major> af0, af1;
            wmma::load_matrix_sync(af0, As + st * AS_H + (wm * 32) * 40 + ks * 16, 40);
            wmma::load_matrix_sync(af1, As + st * AS_H + (wm * 32 + 16) * 40 + ks * 16, 40);
            #pragma unroll
            for (int j = 0; j < 4; j++) {
                wmma::fragment<wmma::matrix_b, 16, 16, 16, __half, wmma::row_major> bf;
                wmma::load_matrix_sync(bf, Bs + st * BS_H + (ks * 16) * 136 + wn * 64 + j * 16, 136);
                wmma::mma_sync(cf[0][j], af0, bf, cf[0][j]);
                wmma::mma_sync(cf[1][j], af1, bf, cf[1][j]);
            }
        }
        if (t < 3) {
            __syncthreads();
            STS((t + 1) & 1);
            __syncthreads();
        }
    }

    /* epilogue: two phases through smem (Cs reuses As/Bs) */
    const int r = tid >> 1;
    const int gm = bm + r;
    const int head = blockIdx.x;                     /* valid for N=512 x-GEMM */
    float ds = 0.f, dd = 0.f;

    #pragma unroll
    for (int ph = 0; ph < 2; ph++) {
        __syncthreads();
        #pragma unroll
        for (int i = 0; i < 2; i++)
            #pragma unroll
            for (int q = 0; q < 2; q++)
                wmma::store_matrix_sync(Cs + (wm * 32 + i * 16) * 72 + wn * 32 + q * 16,
                                        cf[i][ph * 2 + q], 72, wmma::mem_row_major);
        __syncthreads();
        int c0 = (tid & 1) * 32;
        if (gm < M) {
            const float* srow = Cs + r * 72 + c0;
            int colb = (c0 ? 64 : 0) + ph * 32;      /* column within 128 */
            int gnb = bn + colb;
            #pragma unroll
            for (int c = 0; c < 32; c += 4) {
                float4 v = *(const float4*)(srow + c);
                if (bias) {
                    v.x += bias[gnb + c + 0];
                    v.y += bias[gnb + c + 1];
                    v.z += bias[gnb + c + 2];
                    v.w += bias[gnb + c + 3];
                }
                if (av) {
                    float4 a4 = *(const float4*)(av + head * D + colb + c);
                    float4 b4 = *(const float4*)(dv + head * D + colb + c);
                    ds += v.x * a4.x + v.y * a4.y + v.z * a4.z + v.w * a4.w;
                    dd += v.x * b4.x + v.y * b4.y + v.z * b4.z + v.w * b4.w;
                }
                if (sizeof(OutT) == 4) {
                    *(float4*)((float*)C + (long)gm * N + gnb + c) = v;
                } else {
                    __half2 h0 = __floats2half2_rn(v.x, v.y);
                    __half2 h1 = __floats2half2_rn(v.z, v.w);
                    uint2 u; u.x = *(unsigned*)&h0; u.y = *(unsigned*)&h1;
                    *(uint2*)((__half*)C + (long)gm * N + gnb + c) = u;
                }
            }
        }
    }
    if (av && gm < M) {
        ds += __shfl_xor_sync(0xffffffffu, ds, 1);
        dd += __shfl_xor_sync(0xffffffffu, dd, 1);
        if (!(tid & 1)) {
            als_out[(long)gm * NH + head] = ds;
            ald_out[(long)gm * NH + head] = dd;
        }
    }
    #undef LOAD_A
    #undef LOAD_B
    #undef STS
}

/* ---------------- LayerNorm + FiLM ---------------- */
__global__ void k_ln_film(const float* __restrict__ ls, const float* __restrict__ lb,
                          const float* __restrict__ gam, const float* __restrict__ bet) {
    int n = (blockIdx.x * blockDim.x + threadIdx.x) >> 5;
    int lane = threadIdx.x & 31;
    if (n >= NN) return;
    float4 v = *(const float4*)(g_h + n * D + lane * 4);
    float mu = wredsum(v.x + v.y + v.z + v.w) * (1.f / 128.f);
    float d0 = v.x - mu, d1 = v.y - mu, d2 = v.z - mu, d3 = v.w - mu;
    float var = wredsum(d0 * d0 + d1 * d1 + d2 * d2 + d3 * d3) * (1.f / 128.f);
    float rs = rsqrtf(var + 1e-5f);
    float4 lsv = *(const float4*)(ls + lane * 4);
    float4 lbv = *(const float4*)(lb + lane * 4);
    float4 gv = *(const float4*)(gam + lane * 4);
    float4 bv = *(const float4*)(bet + lane * 4);
    float4 o;
    o.x = gv.x * (d0 * rs * lsv.x + lbv.x) + bv.x;
    o.y = gv.y * (d1 * rs * lsv.y + lbv.y) + bv.y;
    o.z = gv.z * (d2 * rs * lsv.z + lbv.z) + bv.z;
    o.w = gv.w * (d3 * rs * lsv.w + lbv.w) + bv.w;
    *(float4*)(g_hm + n * D + lane * 4) = o;
}

/* ---------------- edge attention vectors, all layers ---------------- */
__global__ void k_attvec(const float* __restrict__ gWe, const float* __restrict__ gaedge) {
    int l = blockIdx.x;
    const float* We = gWe + (long)l * EFD * NH * D;
    const float* aedge = gaedge + (long)l * NH * D;
    __shared__ float sv[NH * EFD];
    int t = threadIdx.x;           /* 128 threads */
    int h = t >> 5, f = t & 31;
    float s = 0.f;
    for (int d = 0; d < D; d++) s += We[f * (NH * D) + h * D + d] * aedge[h * D + d];
    sv[h * EFD + f] = s;
    g_v[l * NH * EFD + h * EFD + f] = s;
    __syncthreads();
    if (t < NH) {
        float s2 = 0.f;
        for (int k = 0; k < EFD; k++) s2 += g_eamean[k] * sv[t * EFD + k];
        g_aleself[l * NH + t] = s2;
    }
}

/* ---------------- per-edge attention logit al_e for ALL layers -------------- */
__global__ void k_ale_all(const float* __restrict__ ea) {
    __shared__ float sv[NL * NH * EFD];   /* 768 floats */
    __shared__ float se[128 * 33];
    int t = threadIdx.x;           /* 128 */
    long base = (long)blockIdx.x * 128;
    for (int i = t; i < NL * NH * EFD; i += 128) sv[i] = g_v[i];
    #pragma unroll
    for (int i = 0; i < 32; i++) {
        long li = (long)t + (long)i * 128;
        long gi = base * EFD + li;
        if (gi < (long)NE * EFD) {
            int row = (int)(li >> 5), col = (int)(li & 31);
            se[row * 33 + col] = ea[gi];
        }
    }
    __syncthreads();
    long j = base + t;
    if (j >= NE) return;
    float ev[EFD];
    #pragma unroll
    for (int k = 0; k < EFD; k++) ev[k] = se[t * 33 + k];
    #pragma unroll
    for (int l = 0; l < NL; l++) {
        float s0 = 0.f, s1 = 0.f, s2 = 0.f, s3 = 0.f;
        const float* v = sv + l * NH * EFD;
        #pragma unroll
        for (int k = 0; k < EFD; k++) {
            float e = ev[k];
            s0 += e * v[k];
            s1 += e * v[EFD + k];
            s2 += e * v[2 * EFD + k];
            s3 += e * v[3 * EFD + k];
        }
        float* o = g_ale + ((long)l * NE + j) * NH;
        o[0] = s0; o[1] = s1; o[2] = s2; o[3] = s3;
    }
}

/* ---------------- softmax: logits + max + exp + normalize, warp per node ----
   Writes NORMALIZED weights (w * 0.25 / den) into g_lg (CSR order). */
__global__ void k_softmax(const float* __restrict__ ale_l,
                          const float* __restrict__ aleself_l) {
    int n = (blockIdx.x * blockDim.x + threadIdx.x) >> 5;
    int lane = threadIdx.x & 31;
    if (n >= NN) return;
    int rb = g_rowptr[n], re = g_rowptr[n + 1];
    float4 ad = *(const float4*)(g_ald + (long)n * NH);

    float4 lw[4];
    float4 mx = make_float4(-1e30f, -1e30f, -1e30f, -1e30f);
    int cnt = 0;
    for (int i = rb + lane; i < re; i += 32) {
        int s = g_csrsrc[i], e = g_csreid[i];
        float4 as = *(const float4*)(g_als + (long)s * NH);
        float4 ae = (e < NE) ? *(const float4*)(ale_l + (long)e * NH)
                             : *(const float4*)aleself_l;
        float4 a;
        float t;
        t = as.x + ad.x + ae.x; a.x = t > 0.f ? t : 0.2f * t;
        t = as.y + ad.y + ae.y; a.y = t > 0.f ? t : 0.2f * t;
        t = as.z + ad.z + ae.z; a.z = t > 0.f ? t : 0.2f * t;
        t = as.w + ad.w + ae.w; a.w = t > 0.f ? t : 0.2f * t;
        if (cnt < 4) lw[cnt] = a;
        else *(float4*)(g_lg + (long)i * NH) = a;   /* rare overflow (deg>128) */
        cnt++;
        mx.x = fmaxf(mx.x, a.x); mx.y = fmaxf(mx.y, a.y);
        mx.z = fmaxf(mx.z, a.z); mx.w = fmaxf(mx.w, a.w);
    }
    wredmax4(mx);

    float4 den = make_float4(0.f, 0.f, 0.f, 0.f);
    int m = cnt < 4 ? cnt : 4;
    #pragma unroll 4
    for (int j = 0; j < m; j++) {
        lw[j].x = __expf(lw[j].x - mx.x);
        lw[j].y = __expf(lw[j].y - mx.y);
        lw[j].z = __expf(lw[j].z - mx.z);
        lw[j].w = __expf(lw[j].w - mx.w);
        den.x += lw[j].x; den.y += lw[j].y; den.z += lw[j].z; den.w += lw[j].w;
    }
    for (int i = rb + lane + 128; i < re; i += 32) {     /* overflow part */
        float4 a = *(const float4*)(g_lg + (long)i * NH);
        a.x = __expf(a.x - mx.x); a.y = __expf(a.y - mx.y);
        a.z = __expf(a.z - mx.z); a.w = __expf(a.w - mx.w);
        *(float4*)(g_lg + (long)i * NH) = a;
        den.x += a.x; den.y += a.y; den.z += a.z; den.w += a.w;
    }
    wredsum4(den);
    float4 scl;
    scl.x = 0.25f / (den.x + 1e-16f);
    scl.y = 0.25f / (den.y + 1e-16f);
    scl.z = 0.25f / (den.z + 1e-16f);
    scl.w = 0.25f / (den.w + 1e-16f);

    #pragma unroll 4
    for (int j = 0; j < m; j++) {
        float4 o;
        o.x = lw[j].x * scl.x; o.y = lw[j].y * scl.y;
        o.z = lw[j].z * scl.z; o.w = lw[j].w * scl.w;
        *(float4*)(g_lg + (long)(rb + lane + j * 32) * NH) = o;
    }
    for (int i = rb + lane + 128; i < re; i += 32) {
        float4 a = *(const float4*)(g_lg + (long)i * NH);
        a.x *= scl.x; a.y *= scl.y; a.z *= scl.z; a.w *= scl.w;
        *(float4*)(g_lg + (long)i * NH) = a;
    }
}

/* ---------------- GAT message passing: pure weighted gather ---------------- */
__global__ void k_message(const float* __restrict__ bias) {
    int n = (blockIdx.x * blockDim.x + threadIdx.x) >> 5;
    int lane = threadIdx.x & 31;
    if (n >= NN) return;
    int hh = lane >> 3;
    int dp = (lane & 7) << 4;
    int rb = g_rowptr[n], re = g_rowptr[n + 1];

    float acc[16];
    #pragma unroll
    for (int k = 0; k < 16; k++) acc[k] = 0.f;

    #pragma unroll 2
    for (int i = rb; i < re; i++) {
        int s = g_csrsrc[i];
        float4 wv = *(const float4*)(g_lg + (long)i * NH);
        float w = (hh == 0) ? wv.x : (hh == 1) ? wv.y : (hh == 2) ? wv.z : wv.w;
        const __half* xp = g_x + (((long)s * NH + hh) << 7) + dp;
        uint4 r0 = *(const uint4*)xp;
        uint4 r1 = *(const uint4*)(xp + 8);
        const __half2* hp0 = (const __half2*)&r0;
        const __half2* hp1 = (const __half2*)&r1;
        #pragma unroll
        for (int q = 0; q < 4; q++) {
            float2 f = __half22float2(hp0[q]);
            acc[q * 2 + 0] += w * f.x;
            acc[q * 2 + 1] += w * f.y;
        }
        #pragma unroll
        for (int q = 0; q < 4; q++) {
            float2 f = __half22float2(hp1[q]);
            acc[8 + q * 2 + 0] += w * f.x;
            acc[8 + q * 2 + 1] += w * f.y;
        }
    }
    #pragma unroll
    for (int k = 0; k < 16; k++) {
        float vv = acc[k];
        vv += __shfl_xor_sync(0xffffffffu, vv, 8);
        vv += __shfl_xor_sync(0xffffffffu, vv, 16);
        acc[k] = vv;
    }
    if (lane < 8) {
        #pragma unroll
        for (int k = 0; k < 4; k++) {
            float4 o;
            o.x = fmaxf(acc[k * 4 + 0] + bias[dp + k * 4 + 0], 0.f);
            o.y = fmaxf(acc[k * 4 + 1] + bias[dp + k * 4 + 1], 0.f);
            o.z = fmaxf(acc[k * 4 + 2] + bias[dp + k * 4 + 2], 0.f);
            o.w = fmaxf(acc[k * 4 + 3] + bias[dp + k * 4 + 3], 0.f);
            *(float4*)(g_h + n * D + dp + k * 4) = o;
        }
    }
}

/* ---------------- fused edge head ---------------- */
__global__ void __launch_bounds__(256)
k_edge_head(const int* __restrict__ src, const int* __restrict__ dst,
            const float* __restrict__ W1, const float* __restrict__ b1,
            const float* __restrict__ W2, const float* __restrict__ b2,
            const float* __restrict__ ea, float* __restrict__ out) {
    __shared__ float sW[EFD][128];
    __shared__ float sb[128], sw2[128];
    int tid = threadIdx.x;
    for (int i = tid; i < EFD * 128; i += 256) sW[i >> 7][i & 127] = W1[256 * 128 + i];
    if (tid < 128) { sb[tid] = b1[tid]; sw2[tid] = W2[tid]; }
    __syncthreads();
    float bias2 = b2[0];
    int lane = tid & 31;
    int warp = blockIdx.x * 8 + (tid >> 5);
    int nwarps = gridDim.x * 8;
    const int NG = NE / 4;
    for (int g = warp; g < NG; g += nwarps) {
        int e = g * 4;
        float ev[4];
        float4 tu[4];
        #pragma unroll
        for (int k = 0; k < 4; k++) {
            int s = src[e + k], d = dst[e + k];
            ev[k] = ea[(long)(e + k) * EFD + lane];
            float4 tv = *(const float4*)(g_t + (long)s * D + lane * 4);
            float4 uv = *(const float4*)(g_u + (long)d * D + lane * 4);
            tu[k].x = tv.x + uv.x; tu[k].y = tv.y + uv.y;
            tu[k].z = tv.z + uv.z; tu[k].w = tv.w + uv.w;
        }
        float4 p[4];
        #pragma unroll
        for (int k = 0; k < 4; k++) p[k] = make_float4(0.f, 0.f, 0.f, 0.f);
        #pragma unroll
        for (int j = 0; j < EFD; j++) {
            float4 w = *(const float4*)&sW[j][lane * 4];
            #pragma unroll
            for (int k = 0; k < 4; k++) {
                float bj = __shfl_sync(0xffffffffu, ev[k], j);
                p[k].x += bj * w.x; p[k].y += bj * w.y;
                p[k].z += bj * w.z; p[k].w += bj * w.w;
            }
        }
        float4 bb = *(const float4*)&sb[lane * 4];
        float4 w2 = *(const float4*)&sw2[lane * 4];
        #pragma unroll
        for (int k = 0; k < 4; k++) {
            float z0 = fmaxf(tu[k].x + p[k].x + bb.x, 0.f);
            float z1 = fmaxf(tu[k].y + p[k].y + bb.y, 0.f);
            float z2 = fmaxf(tu[k].z + p[k].z + bb.z, 0.f);
            float z3 = fmaxf(tu[k].w + p[k].w + bb.w, 0.f);
            float s4 = wredsum(z0 * w2.x + z1 * w2.y + z2 * w2.z + z3 * w2.w);
            if (lane == 0) out[e + k] = s4 + bias2;
        }
    }
}

/* ---------------- host orchestration ---------------- */
extern "C" void kernel_launch(void* const* d_in, const int* in_sizes, int n_in,
                              void* d_out, int out_size) {
    const float* x      = (const float*)d_in[0];
    const int*   ei     = (const int*)  d_in[1];
    const float* ea     = (const float*)d_in[2];
    const float* gamma  = (const float*)d_in[3];
    const float* beta   = (const float*)d_in[4];
    const float* embW   = (const float*)d_in[5];
    const float* embb   = (const float*)d_in[6];
    const float* lns    = (const float*)d_in[7];
    const float* lnb    = (const float*)d_in[8];
    const float* gatW   = (const float*)d_in[9];
    const float* asrc   = (const float*)d_in[10];
    const float* adst   = (const float*)d_in[11];
    const float* gWe    = (const float*)d_in[12];
    const float* aedge  = (const float*)d_in[13];
    const float* gbias  = (const float*)d_in[14];
    const float* W1     = (const float*)d_in[15];
    const float* b1     = (const float*)d_in[16];
    const float* W2     = (const float*)d_in[17];
    const float* b2     = (const float*)d_in[18];
    float* out = (float*)d_out;

    const int* src = ei;
    const int* dst = ei + NE;

    float *p_h, *p_hm, *p_t, *p_u, *p_ale, *p_aleself, *p_als, *p_ald;
    __half* p_x;
    cudaGetSymbolAddress((void**)&p_h,  g_h);
    cudaGetSymbolAddress((void**)&p_hm, g_hm);
    cudaGetSymbolAddress((void**)&p_x,  g_x);
    cudaGetSymbolAddress((void**)&p_t,  g_t);
    cudaGetSymbolAddress((void**)&p_u,  g_u);
    cudaGetSymbolAddress((void**)&p_ale, g_ale);
    cudaGetSymbolAddress((void**)&p_aleself, g_aleself);
    cudaGetSymbolAddress((void**)&p_als, g_als);
    cudaGetSymbolAddress((void**)&p_ald, g_ald);

    /* edge-attr mean, per-layer edge attention vectors, all-layer al_e */
    k_eamean1<<<256, 128>>>(ea);
    k_eamean2<<<1, 32>>>();
    k_attvec<<<NL, 128>>>(gWe, aedge);
    k_ale_all<<<(NE + 127) / 128, 128>>>(ea);

    /* CSR build */
    k_init_counts<<<(NN + 255) / 256, 256>>>();
    k_count<<<(NE + 255) / 256, 256>>>(dst);
    int nb = (NN + 1023) / 1024;
    k_scan_local<<<nb, 1024>>>();
    k_scan_fixup<<<1, 32>>>(nb);
    k_scan_add<<<(NN + 255) / 256, 256>>>();
    k_scatter_edges<<<(NE + 255) / 256, 256>>>(src, dst);
    k_scatter_self<<<(NN + 255) / 256, 256>>>();

    const int MB = (NN + 127) / 128;   /* 196 */

    /* embed: h = x @ embW + embb */
    k_gemm_mma<float><<<dim3(1, MB), 256>>>(x, embW, p_h, NN, 128, embb,
                                            (const float*)0, (const float*)0,
                                            (float*)0, (float*)0);

    /* layers */
    for (int l = 0; l < NL; l++) {
        k_ln_film<<<(NN * 32 + 255) / 256, 256>>>(lns + l * D, lnb + l * D,
                                                  gamma + l * D, beta + l * D);
        k_gemm_mma<__half><<<dim3(4, MB), 256>>>(p_hm, gatW + (long)l * D * NH * D,
                                                 p_x, NN, 512, (const float*)0,
                                                 asrc + l * NH * D, adst + l * NH * D,
                                                 p_als, p_ald);
        k_softmax<<<(NN * 32 + 255) / 256, 256>>>(p_ale + (long)l * NE * NH,
                                                  p_aleself + l * NH);
        k_message<<<(NN * 32 + 255) / 256, 256>>>(gbias + l * D);
    }

    /* head */
    k_gemm_mma<float><<<dim3(1, MB), 256>>>(p_h, W1, p_t, NN, 128, (const float*)0,
                                            (const float*)0, (const float*)0,
                                            (float*)0, (float*)0);
    k_gemm_mma<float><<<dim3(1, MB), 256>>>(p_h, W1 + 128 * 128, p_u, NN, 128,
                                            (const float*)0,
                                            (const float*)0, (const float*)0,
                                            (float*)0, (float*)0);
    k_edge_head<<<2048, 256>>>(src, dst, W1, b1, W2, b2, ea, out);
}